// round 15
// baseline (speedup 1.0000x reference)
#include <cuda_runtime.h>
#include <cuda_bf16.h>
#include <math.h>
#include <stdint.h>

#define BN_    4
#define LL     2048
#define DMODEL 512
#define DI     1024
#define DI2    2048
#define DST    16
#define DTR    64
#define XD     96
#define NTOK   8192   // B * L

// tcgen05 only exists on the arch-specific target (sm_103a / sm_100a).
#if defined(__CUDA_ARCH_FEAT_SM103_ALL) || defined(__CUDA_ARCH_FEAT_SM100_ALL)
#define HAS_TC5 1
#endif

typedef __nv_bfloat16 bf16;

// ---------------- scratch (device globals: no allocation allowed) ----------------
__device__ float g_xp  [(size_t)NTOK * DI2];
__device__ float g_xz  [2][(size_t)NTOK * DI2];
__device__ float g_xma [2][(size_t)NTOK * DI];
__device__ float g_xdbl[2][(size_t)NTOK * XD];
__device__ float g_dt  [2][(size_t)NTOK * DI];
// bf16 hi/lo pre-split GEMM operands
__device__ bf16 g_xnh[(size_t)NTOK * DMODEL], g_xnl[(size_t)NTOK * DMODEL];
__device__ bf16 g_xah[(size_t)NTOK * DI],     g_xal[(size_t)NTOK * DI];
__device__ bf16 g_xmh[2][(size_t)NTOK * DI],  g_xml[2][(size_t)NTOK * DI];
__device__ bf16 g_xdh[2][(size_t)NTOK * XD],  g_xdl[2][(size_t)NTOK * XD];
__device__ bf16 g_ygh[2][(size_t)NTOK * DI],  g_ygl[2][(size_t)NTOK * DI];
__device__ bf16 g_ymh[(size_t)NTOK * DI2],    g_yml[(size_t)NTOK * DI2];
// all weights pre-split once, persistent slots (8,716,288 elems)
#define WTOT 8716288
__device__ bf16 g_wH[WTOT], g_wL[WTOT];

__device__ __forceinline__ float siluf(float x)     { return x / (1.f + __expf(-x)); }
__device__ __forceinline__ float softplusf(float x) { return x > 20.f ? x : log1pf(__expf(x)); }

__device__ __forceinline__ uint32_t pack_bf16x2(float x, float y) {
    uint32_t r;
    asm("cvt.rn.bf16x2.f32 %0, %1, %2;" : "=r"(r) : "f"(y), "f"(x));  // {lo=x, hi=y}
    return r;
}
__device__ __forceinline__ void split2(float x, float y, uint32_t& h, uint32_t& l) {
    h = pack_bf16x2(x, y);
    const float rx = __uint_as_float(h << 16);
    const float ry = __uint_as_float(h & 0xffff0000u);
    l = pack_bf16x2(x - rx, y - ry);
}

// ---------------- weight split kernels ----------------
__global__ void split_kernel(const float* __restrict__ in, bf16* __restrict__ hi,
                             bf16* __restrict__ lo, int n4)
{
    const int i = blockIdx.x * 256 + threadIdx.x;
    if (i < n4) {
        const float4 v = ((const float4*)in)[i];
        uint32_t h0, l0, h1, l1;
        split2(v.x, v.y, h0, l0);
        split2(v.z, v.w, h1, l1);
        ((uint2*)hi)[i] = make_uint2(h0, h1);
        ((uint2*)lo)[i] = make_uint2(l0, l1);
    }
}

struct SplitJobs {
    const float* src[9];
    size_t off[9];
    int n4[9];
};

__global__ void split_many(SplitJobs j, bf16* __restrict__ hi, bf16* __restrict__ lo)
{
    const int job = blockIdx.y;
    const int i = blockIdx.x * 256 + threadIdx.x;
    if (i < j.n4[job]) {
        const float4 v = ((const float4*)j.src[job])[i];
        uint32_t h0, l0, h1, l1;
        split2(v.x, v.y, h0, l0);
        split2(v.z, v.w, h1, l1);
        ((uint2*)(hi + j.off[job]))[i] = make_uint2(h0, h1);
        ((uint2*)(lo + j.off[job]))[i] = make_uint2(l0, l1);
    }
}

// ---------------- LayerNorm -> split bf16 ----------------
__global__ void ln_kernel(const float* __restrict__ x, const float* __restrict__ gg,
                          const float* __restrict__ bb,
                          bf16* __restrict__ hi, bf16* __restrict__ lo)
{
    __shared__ float red[8];
    const int row = blockIdx.x;
    const int t   = threadIdx.x;
    float4 v = ((const float4*)(x + (size_t)row * DMODEL))[t];
    float s = v.x + v.y + v.z + v.w;
#pragma unroll
    for (int o = 16; o; o >>= 1) s += __shfl_xor_sync(0xffffffffu, s, o);
    if ((t & 31) == 0) red[t >> 5] = s;
    __syncthreads();
    const float mu = (red[0] + red[1] + red[2] + red[3]) * (1.f / DMODEL);
    const float dx = v.x - mu, dy = v.y - mu, dz = v.z - mu, dw = v.w - mu;
    float vs = dx*dx + dy*dy + dz*dz + dw*dw;
#pragma unroll
    for (int o = 16; o; o >>= 1) vs += __shfl_xor_sync(0xffffffffu, vs, o);
    if ((t & 31) == 0) red[4 + (t >> 5)] = vs;
    __syncthreads();
    const float var = (red[4] + red[5] + red[6] + red[7]) * (1.f / DMODEL);
    const float inv = rsqrtf(var + 1e-5f);
    const int i0 = t << 2;
    float ox = dx * inv * gg[i0+0] + bb[i0+0];
    float oy = dy * inv * gg[i0+1] + bb[i0+1];
    float oz = dz * inv * gg[i0+2] + bb[i0+2];
    float ow = dw * inv * gg[i0+3] + bb[i0+3];
    uint32_t h0, l0, h1, l1;
    split2(ox, oy, h0, l0);
    split2(oz, ow, h1, l1);
    ((uint2*)(hi + (size_t)row * DMODEL))[t] = make_uint2(h0, h1);
    ((uint2*)(lo + (size_t)row * DMODEL))[t] = make_uint2(l0, l1);
}

#ifdef HAS_TC5
// ---------------- tcgen05 helpers ----------------
__device__ __forceinline__ uint32_t smem_u32(const void* p) {
    uint32_t a;
    asm("{ .reg .u64 t; cvta.to.shared.u64 t, %1; cvt.u32.u64 %0, t; }" : "=r"(a) : "l"(p));
    return a;
}
__device__ __forceinline__ uint32_t elect1() {
    uint32_t p;
    asm volatile("{\n\t.reg .pred p;\n\telect.sync _|p, 0xFFFFFFFF;\n\tselp.b32 %0, 1, 0, p;\n\t}"
                 : "=r"(p));
    return p;
}
__device__ __forceinline__ uint32_t swz(uint32_t off) { return off ^ ((off >> 3) & 0x70); }

__device__ __forceinline__ void cp16(uint32_t dst, const void* src, int sz) {
    asm volatile("cp.async.cg.shared.global [%0], [%1], 16, %2;"
                 :: "r"(dst), "l"(src), "r"(sz) : "memory");
}

// SW128 K-major smem descriptor (Blackwell): layout=2, version=1, SBO=64, LBO=1
static __device__ __forceinline__ uint64_t mkdesc(uint32_t addr) {
    const uint64_t base = (2ull << 61) | (1ull << 46) | (64ull << 32) | (1ull << 16);
    return base | ((addr >> 4) & 0x3FFFu);
}

__device__ __forceinline__ void mma_f16_ss(uint32_t d, uint64_t a, uint64_t b,
                                           uint32_t idesc, uint32_t en) {
    asm volatile(
        "{\n\t.reg .pred p;\n\tsetp.ne.u32 p, %4, 0;\n\t"
        "tcgen05.mma.cta_group::1.kind::f16 [%0], %1, %2, %3, {%5,%5,%5,%5}, p;\n\t}"
        :: "r"(d), "l"(a), "l"(b), "r"(idesc), "r"(en), "r"(0u) : "memory");
}

__device__ __forceinline__ void mbar_wait(uint32_t mbar, uint32_t parity) {
    asm volatile(
        "{\n\t.reg .pred P;\n\t"
        "W_%=:\n\t"
        "mbarrier.try_wait.parity.acquire.cta.shared::cta.b64 P, [%0], %1, 0x989680;\n\t"
        "@P bra.uni D_%=;\n\t"
        "bra.uni W_%=;\n\t"
        "D_%=:\n\t}"
        :: "r"(mbar), "r"(parity) : "memory");
}

#define TC_LD32(r, addr) \
    asm volatile( \
        "tcgen05.ld.sync.aligned.32x32b.x32.b32 " \
        "{%0, %1, %2, %3, %4, %5, %6, %7, " \
        " %8, %9, %10, %11, %12, %13, %14, %15, " \
        " %16, %17, %18, %19, %20, %21, %22, %23, " \
        " %24, %25, %26, %27, %28, %29, %30, %31}, [%32];" \
        : "=r"((r)[0]),  "=r"((r)[1]),  "=r"((r)[2]),  "=r"((r)[3]), \
          "=r"((r)[4]),  "=r"((r)[5]),  "=r"((r)[6]),  "=r"((r)[7]), \
          "=r"((r)[8]),  "=r"((r)[9]),  "=r"((r)[10]), "=r"((r)[11]), \
          "=r"((r)[12]), "=r"((r)[13]), "=r"((r)[14]), "=r"((r)[15]), \
          "=r"((r)[16]), "=r"((r)[17]), "=r"((r)[18]), "=r"((r)[19]), \
          "=r"((r)[20]), "=r"((r)[21]), "=r"((r)[22]), "=r"((r)[23]), \
          "=r"((r)[24]), "=r"((r)[25]), "=r"((r)[26]), "=r"((r)[27]), \
          "=r"((r)[28]), "=r"((r)[29]), "=r"((r)[30]), "=r"((r)[31]) \
        : "r"(addr))
#else
__device__ __forceinline__ void mma_bf16(float* c, const uint32_t* a, const uint32_t* b) {
    asm volatile("mma.sync.aligned.m16n8k16.row.col.f32.bf16.bf16.f32 "
        "{%0,%1,%2,%3}, {%4,%5,%6,%7}, {%8,%9}, {%0,%1,%2,%3};"
        : "+f"(c[0]), "+f"(c[1]), "+f"(c[2]), "+f"(c[3])
        : "r"(a[0]), "r"(a[1]), "r"(a[2]), "r"(a[3]), "r"(b[0]), "r"(b[1]));
}
#endif

// ---------------- GEMM: C[M,N] = (Ah+Al)[M,K] @ (Wh+Wl)[N,K]^T, 3-pass split -------
// 128x256 tiles (N=256 single cg1 dispatch), BK=64, cp.async fills. 97KB smem -> 2 CTAs/SM.
// gridDim.z batches directions. M mult of 128, K mult of 64 (fallback: 16).
// EPI: 0 none, 1 softplus(acc+aux[n]), 2 acc+aux[m*N+n], 3 fp32 C + split (Ch,Cl),
//      4 gated split:  split(acc * silu(aux[m*DI2+DI+col])) -> Ch/Cl at [m*DI2+col]
//        (Ch/Cl pre-shifted by z*chStrideZ; no fp32 C write)
#define SM_AH 1024
#define SM_AL 17408
#define SM_BH 33792
#define SM_BL 66560
#define SM_TOT 99328

template<int EPI>
__global__ void __launch_bounds__(128)
gemm5(const bf16* __restrict__ Ah, const bf16* __restrict__ Al, int lda, size_t aStrideZ,
      const bf16* __restrict__ Wh, const bf16* __restrict__ Wl, size_t wStrideZ,
      float* __restrict__ C, size_t cStrideZ, int N, int K,
      const float* __restrict__ aux0, const float* __restrict__ aux1,
      bf16* __restrict__ Ch, bf16* __restrict__ Cl, size_t chStrideZ)
{
    const int z = blockIdx.z;
    Ah += (size_t)z * aStrideZ;  Al += (size_t)z * aStrideZ;
    Wh += (size_t)z * wStrideZ;  Wl += (size_t)z * wStrideZ;
    C  += (size_t)z * cStrideZ;
    const float* aux = z ? aux1 : aux0;
    if (EPI >= 3) { Ch += (size_t)z * chStrideZ; Cl += (size_t)z * chStrideZ; }

#ifdef HAS_TC5
    extern __shared__ __align__(1024) char sm[];
    const uint32_t sb = smem_u32(sm);
    const int tid = threadIdx.x, warp = tid >> 5, lane = tid & 31;
    const int m0 = blockIdx.y << 7, n0 = blockIdx.x << 8;

    if (warp == 0) {
        asm volatile("tcgen05.alloc.cta_group::1.sync.aligned.shared::cta.b32 [%0], %1;"
                     :: "r"(sb), "r"(256u) : "memory");
        asm volatile("tcgen05.relinquish_alloc_permit.cta_group::1.sync.aligned;");
    }
    if (tid == 0)
        asm volatile("mbarrier.init.shared.b64 [%0], %1;" :: "r"(sb + 8), "r"(1u) : "memory");
    __syncthreads();
    uint32_t tmem;
    asm volatile("ld.shared.b32 %0, [%1];" : "=r"(tmem) : "r"(sb));

    const uint32_t idesc = 0x8400490u;   // M=128, N=256, bf16 x bf16 -> f32
    uint32_t phase = 0;

    for (int k0 = 0; k0 < K; k0 += 64) {
        // A tiles: 128 rows x 128B (hi + lo)
#pragma unroll
        for (int i = 0; i < 8; i++) {
            const int idx = tid + (i << 7);          // 0..1023
            const int r   = idx >> 3;                // 0..127
            const int ch  = idx & 7;
            const uint32_t sw = swz((uint32_t)(r * 128 + ch * 16));
            const size_t aoff = (size_t)(m0 + r) * lda + k0 + (ch << 3);
            cp16(sb + SM_AH + sw, Ah + aoff, 16);
            cp16(sb + SM_AL + sw, Al + aoff, 16);
        }
        // B tiles: 256 rows x 128B (hi + lo)
#pragma unroll
        for (int i = 0; i < 16; i++) {
            const int idx = tid + (i << 7);          // 0..2047
            const int r   = idx >> 3;                // 0..255
            const int ch  = idx & 7;
            const uint32_t sw = swz((uint32_t)(r * 128 + ch * 16));
            const int rb  = (n0 + r < N) ? (n0 + r) : 0;
            const int bsz = (n0 + r < N) ? 16 : 0;
            const size_t boff = (size_t)rb * K + k0 + (ch << 3);
            cp16(sb + SM_BH + sw, Wh + boff, bsz);
            cp16(sb + SM_BL + sw, Wl + boff, bsz);
        }
        asm volatile("cp.async.commit_group;" ::: "memory");
        asm volatile("cp.async.wait_group 0;" ::: "memory");
        asm volatile("fence.proxy.async.shared::cta;" ::: "memory");
        __syncthreads();

        if (warp == 0 && elect1()) {
            const uint64_t ah = mkdesc(sb + SM_AH), al = mkdesc(sb + SM_AL);
            const uint64_t bh = mkdesc(sb + SM_BH), bl = mkdesc(sb + SM_BL);
#pragma unroll
            for (int kc = 0; kc < 4; kc++) {
                mma_f16_ss(tmem, ah + kc * 2, bh + kc * 2, idesc, (k0 | kc) != 0);
                mma_f16_ss(tmem, ah + kc * 2, bl + kc * 2, idesc, 1u);
                mma_f16_ss(tmem, al + kc * 2, bh + kc * 2, idesc, 1u);
            }
            asm volatile(
                "tcgen05.commit.cta_group::1.mbarrier::arrive::one.shared::cluster.b64 [%0];"
                :: "r"(sb + 8) : "memory");
        }
        mbar_wait(sb + 8, phase);
        phase ^= 1;
    }

    asm volatile("tcgen05.fence::after_thread_sync;" ::: "memory");

    const int m = m0 + warp * 32 + lane;
#pragma unroll
    for (int base = 0; base < 256; base += 32) {
        uint32_t r[32];
        TC_LD32(r, tmem + base);
        asm volatile("tcgen05.wait::ld.sync.aligned;" ::: "memory");
#pragma unroll
        for (int j = 0; j < 32; j += 4) {
            const int col = n0 + base + j;
            if (col < N) {
                float4 v = make_float4(__uint_as_float(r[j]),   __uint_as_float(r[j+1]),
                                       __uint_as_float(r[j+2]), __uint_as_float(r[j+3]));
                if (EPI == 1) {
                    const float4 b = *(const float4*)(aux + col);
                    v.x = softplusf(v.x + b.x); v.y = softplusf(v.y + b.y);
                    v.z = softplusf(v.z + b.z); v.w = softplusf(v.w + b.w);
                }
                if (EPI == 2) {
                    const float4 a4 = *(const float4*)(aux + (size_t)m * N + col);
                    v.x += a4.x; v.y += a4.y; v.z += a4.z; v.w += a4.w;
                }
                if (EPI == 4) {
                    const float4 g4 = *(const float4*)(aux + (size_t)m * DI2 + DI + col);
                    v.x *= siluf(g4.x); v.y *= siluf(g4.y);
                    v.z *= siluf(g4.z); v.w *= siluf(g4.w);
                    uint32_t h0, l0, h1, l1;
                    split2(v.x, v.y, h0, l0);
                    split2(v.z, v.w, h1, l1);
                    *(uint2*)(Ch + (size_t)m * DI2 + col) = make_uint2(h0, h1);
                    *(uint2*)(Cl + (size_t)m * DI2 + col) = make_uint2(l0, l1);
                } else {
                    *(float4*)(C + (size_t)m * N + col) = v;
                    if (EPI == 3) {
                        uint32_t h0, l0, h1, l1;
                        split2(v.x, v.y, h0, l0);
                        split2(v.z, v.w, h1, l1);
                        *(uint2*)(Ch + (size_t)m * N + col) = make_uint2(h0, h1);
                        *(uint2*)(Cl + (size_t)m * N + col) = make_uint2(l0, l1);
                    }
                }
            }
        }
    }

    __syncthreads();
    if (tid == 0)
        asm volatile("mbarrier.inval.shared.b64 [%0];" :: "r"(sb + 8) : "memory");
    __syncthreads();
    if (warp == 0)
        asm volatile("tcgen05.dealloc.cta_group::1.sync.aligned.b32 %0, %1;"
                     :: "r"(tmem), "r"(256u));
#else
    // ================= mma.sync fallback (compile-only for non-'a' pass) ============
    __shared__ uint32_t sAh[8][136], sAl[8][136], sBh[8][136], sBl[8][136];
    const int tid  = threadIdx.x;
    const int m0   = blockIdx.y << 7;
    const int lane = tid & 31, warp = tid >> 5;
    const int wm = (warp >> 1) << 6, wn = (warp & 1) << 6;
    const int g  = lane >> 2,  t  = lane & 3;

    for (int nh = 0; nh < 2; nh++) {
        const int n0 = (blockIdx.x << 8) + (nh << 7);
        __syncthreads();
        float acc[4][8][4];
#pragma unroll
        for (int i = 0; i < 4; i++)
#pragma unroll
            for (int j = 0; j < 8; j++)
#pragma unroll
                for (int q = 0; q < 4; q++) acc[i][j][q] = 0.f;

#pragma unroll 1
        for (int k0 = 0; k0 < K; k0 += 16) {
#pragma unroll
            for (int i = 0; i < 8; i++) {
                const int idx = tid + (i << 7);
                const int r   = idx >> 3;
                const int k2  = idx & 7;
                sAh[k2][r] = *(const uint32_t*)(Ah + (size_t)(m0 + r) * lda + k0 + k2 * 2);
                sAl[k2][r] = *(const uint32_t*)(Al + (size_t)(m0 + r) * lda + k0 + k2 * 2);
                uint32_t bh = 0, bl = 0;
                if (n0 + r < N) {
                    bh = *(const uint32_t*)(Wh + (size_t)(n0 + r) * K + k0 + k2 * 2);
                    bl = *(const uint32_t*)(Wl + (size_t)(n0 + r) * K + k0 + k2 * 2);
                }
                sBh[k2][r] = bh; sBl[k2][r] = bl;
            }
            __syncthreads();

            uint32_t bh[8][2], bl[8][2];
#pragma unroll
            for (int nt = 0; nt < 8; nt++) {
                const int nb = wn + (nt << 3) + g;
                bh[nt][0] = sBh[t][nb];     bh[nt][1] = sBh[t+4][nb];
                bl[nt][0] = sBl[t][nb];     bl[nt][1] = sBl[t+4][nb];
            }
#pragma unroll
            for (int mt = 0; mt < 4; mt++) {
                const int mb = wm + (mt << 4) + g;
                uint32_t ah[4] = { sAh[t][mb], sAh[t][mb+8], sAh[t+4][mb], sAh[t+4][mb+8] };
                uint32_t al[4] = { sAl[t][mb], sAl[t][mb+8], sAl[t+4][mb], sAl[t+4][mb+8] };
#pragma unroll
                for (int nt = 0; nt < 8; nt++) {
                    mma_bf16(acc[mt][nt], ah, bh[nt]);
                    mma_bf16(acc[mt][nt], ah, bl[nt]);
                    mma_bf16(acc[mt][nt], al, bh[nt]);
                }
            }
            __syncthreads();
        }

#pragma unroll
        for (int mt = 0; mt < 4; mt++) {
            const int r0 = m0 + wm + (mt << 4) + g;
#pragma unroll
            for (int nt = 0; nt < 8; nt++) {
                const int col = n0 + wn + (nt << 3) + (t << 1);
                if (col < N) {
                    float v0 = acc[mt][nt][0], v1 = acc[mt][nt][1];
                    float v2 = acc[mt][nt][2], v3 = acc[mt][nt][3];
                    if (EPI == 1) {
                        const float b0 = __ldg(&aux[col]), b1 = __ldg(&aux[col+1]);
                        v0 = softplusf(v0 + b0); v1 = softplusf(v1 + b1);
                        v2 = softplusf(v2 + b0); v3 = softplusf(v3 + b1);
                    }
                    if (EPI == 2) {
                        const float2 a0 = *(const float2*)(aux + (size_t)r0 * N + col);
                        const float2 a1 = *(const float2*)(aux + (size_t)(r0+8) * N + col);
                        v0 += a0.x; v1 += a0.y; v2 += a1.x; v3 += a1.y;
                    }
                    if (EPI == 4) {
                        const float2 g0 = *(const float2*)(aux + (size_t)r0 * DI2 + DI + col);
                        const float2 g1 = *(const float2*)(aux + (size_t)(r0+8) * DI2 + DI + col);
                        v0 *= siluf(g0.x); v1 *= siluf(g0.y);
                        v2 *= siluf(g1.x); v3 *= siluf(g1.y);
                        uint32_t h, l;
                        split2(v0, v1, h, l);
                        *(uint32_t*)(Ch + (size_t)r0 * DI2 + col) = h;
                        *(uint32_t*)(Cl + (size_t)r0 * DI2 + col) = l;
                        split2(v2, v3, h, l);
                        *(uint32_t*)(Ch + (size_t)(r0+8) * DI2 + col) = h;
                        *(uint32_t*)(Cl + (size_t)(r0+8) * DI2 + col) = l;
                    } else {
                        *(float2*)(C + (size_t)r0     * N + col) = make_float2(v0, v1);
                        *(float2*)(C + (size_t)(r0+8) * N + col) = make_float2(v2, v3);
                        if (EPI == 3) {
                            uint32_t h, l;
                            split2(v0, v1, h, l);
                            *(uint32_t*)(Ch + (size_t)r0 * N + col) = h;
                            *(uint32_t*)(Cl + (size_t)r0 * N + col) = l;
                            split2(v2, v3, h, l);
                            *(uint32_t*)(Ch + (size_t)(r0+8) * N + col) = h;
                            *(uint32_t*)(Cl + (size_t)(r0+8) * N + col) = l;
                        }
                    }
                }
            }
        }
    }
#endif
}

// ---------------- depthwise conv (K=4) + SiLU + split, float4, z = direction -------
__global__ void conv_silu_kernel(const float* __restrict__ in, int ldin, size_t inStrideZ,
                                 const float* __restrict__ w0, const float* __restrict__ w1,
                                 const float* __restrict__ b0, const float* __restrict__ b1,
                                 float* __restrict__ outf, size_t outfStrideZ,
                                 bf16* __restrict__ outh, bf16* __restrict__ outl,
                                 size_t outStrideZ)
{
    const int z = blockIdx.z;
    const float* inp  = in + (size_t)z * inStrideZ;
    const float* w    = z ? w1 : w0;
    const float* bias = z ? b1 : b0;
    bf16* oh = outh + (size_t)z * outStrideZ;
    bf16* ol = outl + (size_t)z * outStrideZ;

    const int idx4 = blockIdx.x * 256 + threadIdx.x;
    const int dq   = idx4 & (DI / 4 - 1);
    const int tok  = idx4 >> 8;
    const int l    = tok & (LL - 1);
    const int dd   = dq << 2;
    const float* base = inp + (size_t)(tok - l) * ldin + dd;

    float wr[4][4];
    *(float4*)wr[0] = *(const float4*)(w + (dd+0)*4);
    *(float4*)wr[1] = *(const float4*)(w + (dd+1)*4);
    *(float4*)wr[2] = *(const float4*)(w + (dd+2)*4);
    *(float4*)wr[3] = *(const float4*)(w + (dd+3)*4);
    float4 acc = *(const float4*)(bias + dd);

    if (!z) {
#pragma unroll
        for (int k = 0; k < 4; k++) {
            const int ls = l - 3 + k;
            if (ls >= 0) {
                const float4 v = *(const float4*)(base + (size_t)ls * ldin);
                acc.x = fmaf(v.x, wr[0][k], acc.x);
                acc.y = fmaf(v.y, wr[1][k], acc.y);
                acc.z = fmaf(v.z, wr[2][k], acc.z);
                acc.w = fmaf(v.w, wr[3][k], acc.w);
            }
        }
    } else {
#pragma unroll
        for (int j = 0; j < 4; j++) {
            const int ls = l + j;
            if (ls < LL) {
                const float4 v = *(const float4*)(base + (size_t)ls * ldin);
                acc.x = fmaf(v.x, wr[0][3-j], acc.x);
                acc.y = fmaf(v.y, wr[1][3-j], acc.y);
                acc.z = fmaf(v.z, wr[2][3-j], acc.z);
                acc.w = fmaf(v.w, wr[3][3-j], acc.w);
            }
        }
    }
    float4 s = make_float4(siluf(acc.x), siluf(acc.y), siluf(acc.z), siluf(acc.w));
    if (outf) ((float4*)(outf + (size_t)z * outfStrideZ))[idx4] = s;
    uint32_t h0, l0, h1, l1;
    split2(s.x, s.y, h0, l0);
    split2(s.z, s.w, h1, l1);
    ((uint2*)oh)[idx4] = make_uint2(h0, h1);
    ((uint2*)ol)[idx4] = make_uint2(l0, l1);
}

// ---------------- selective scan + fused gating, z = direction ----------------
__global__ __launch_bounds__(256) void scan_kernel(
    const float* __restrict__ u, size_t uStrideZ,
    const float* __restrict__ dt, size_t dtStrideZ,
    const float* __restrict__ xdbl, size_t xdStrideZ,
    const float* __restrict__ xz, size_t xzStrideZ,
    const float* __restrict__ Alog0, const float* __restrict__ Alog1,
    const float* __restrict__ Dp0, const float* __restrict__ Dp1,
    bf16* __restrict__ ygh, bf16* __restrict__ ygl, size_t ygStrideZ)
{
    __shared__ float s_u[64][16], s_dt[64][16], s_B[64][16], s_C[64][16], s_y[64][16];
    const int z = blockIdx.z;
    const int backward = z;
    const float* up  = u + (size_t)z * uStrideZ;
    const float* dtp = dt + (size_t)z * dtStrideZ;
    const float* xdp = xdbl + (size_t)z * xdStrideZ;
    const float* xzp = xz + (size_t)z * xzStrideZ;
    const float* Alog = z ? Alog1 : Alog0;
    const float* Dp   = z ? Dp1   : Dp0;
    bf16* yh = ygh + (size_t)z * ygStrideZ;
    bf16* yl = ygl + (size_t)z * ygStrideZ;

    const int b     = blockIdx.x >> 6;
    const int dbase = (blockIdx.x & 63) << 4;
    const int tid = threadIdx.x;
    const int dl  = tid >> 4;
    const int n   = tid & 15;
    const int d   = dbase + dl;
    const float a    = -expf(Alog[d * DST + n]);
    const float Dloc = Dp[d];
    float h = 0.f;
    const size_t brow = (size_t)b * LL;

    for (int chunk = 0; chunk < LL / 64; chunk++) {
        const int c0 = chunk << 6;
#pragma unroll
        for (int i = 0; i < 4; i++) {
            const int ii = tid + (i << 8);
            const int tt = ii >> 4, dc = ii & 15;
            const int t = c0 + tt;
            const int l = backward ? (LL - 1 - t) : t;
            const size_t roff = brow + l;
            s_u [tt][dc] = up [roff * DI + dbase + dc];
            s_dt[tt][dc] = dtp[roff * DI + dbase + dc];
            s_B [tt][dc] = xdp[roff * XD + 64 + dc];
            s_C [tt][dc] = xdp[roff * XD + 80 + dc];
        }
        __syncthreads();
#pragma unroll 8
        for (int tt = 0; tt < 64; tt++) {
            const float dtv = s_dt[tt][dl];
            const float uv  = s_u [tt][dl];
            const float dA  = __expf(dtv * a);
            const float db  = dtv * uv * s_B[tt][n];
            h = fmaf(dA, h, db);
            float yp = h * s_C[tt][n];
            yp += __shfl_xor_sync(0xffffffffu, yp, 8);
            yp += __shfl_xor_sync(0xffffffffu, yp, 4);
            yp += __shfl_xor_sync(0xffffffffu, yp, 2);
            yp += __shfl_xor_sync(0xffffffffu, yp, 1);
            if (n == 0) s_y[tt][dl] = fmaf(uv, Dloc, yp);
        }
        __syncthreads();
#pragma unroll
        for (int i = 0; i < 4; i++) {
            const int ii = tid + (i << 8);
            const int tt = ii >> 4, dc = ii & 15;
            const int t = c0 + tt;
            const int l = backward ? (LL - 1 - t) : t;
            const size_t roff = brow + l;
            const float zz = xzp[roff * DI2 + DI + dbase + dc];
            const float v = s_y[tt][dc] * siluf(zz);
            const bf16 hv = __float2bfloat16(v);
            yh[roff * DI + dbase + dc] = hv;
            yl[roff * DI + dbase + dc] = __float2bfloat16(v - __bfloat162float(hv));
        }
        __syncthreads();
    }
}

// ---------------- host ----------------
extern "C" void kernel_launch(void* const* d_in, const int* in_sizes, int n_in,
                              void* d_out, int out_size)
{
    const float* x      = (const float*)d_in[0];
    const float* norm_g = (const float*)d_in[1];
    const float* norm_b = (const float*)d_in[2];
    const float* in_w   = (const float*)d_in[3];
    const float* conv_w = (const float*)d_in[4];
    const float* conv_b = (const float*)d_in[5];
    const float* out_w  = (const float*)d_in[6];
    const float* P[2][9];
    for (int p = 0; p < 2; p++)
        for (int i = 0; i < 9; i++)
            P[p][i] = (const float*)d_in[7 + p * 9 + i];
    // P[p]: 0 in_w, 1 conv_w, 2 conv_b, 3 xp_w, 4 dt_w, 5 dt_b, 6 Alog, 7 D, 8 out_w

    cudaFuncSetAttribute(gemm5<0>, cudaFuncAttributeMaxDynamicSharedMemorySize, SM_TOT);
    cudaFuncSetAttribute(gemm5<1>, cudaFuncAttributeMaxDynamicSharedMemorySize, SM_TOT);
    cudaFuncSetAttribute(gemm5<2>, cudaFuncAttributeMaxDynamicSharedMemorySize, SM_TOT);
    cudaFuncSetAttribute(gemm5<3>, cudaFuncAttributeMaxDynamicSharedMemorySize, SM_TOT);
    cudaFuncSetAttribute(gemm5<4>, cudaFuncAttributeMaxDynamicSharedMemorySize, SM_TOT);

    float *xp, *xz, *xma, *xdbl, *dtb;
    bf16 *xnh, *xnl, *xah, *xal, *xmh, *xml, *xdh, *xdl, *ygh, *ygl, *ymh, *yml, *wH, *wL;
    cudaGetSymbolAddress((void**)&xp,   g_xp);
    cudaGetSymbolAddress((void**)&xz,   g_xz);
    cudaGetSymbolAddress((void**)&xma,  g_xma);
    cudaGetSymbolAddress((void**)&xdbl, g_xdbl);
    cudaGetSymbolAddress((void**)&dtb,  g_dt);
    cudaGetSymbolAddress((void**)&xnh,  g_xnh);  cudaGetSymbolAddress((void**)&xnl, g_xnl);
    cudaGetSymbolAddress((void**)&xah,  g_xah);  cudaGetSymbolAddress((void**)&xal, g_xal);
    cudaGetSymbolAddress((void**)&xmh,  g_xmh);  cudaGetSymbolAddress((void**)&xml, g_xml);
    cudaGetSymbolAddress((void**)&xdh,  g_xdh);  cudaGetSymbolAddress((void**)&xdl, g_xdl);
    cudaGetSymbolAddress((void**)&ygh,  g_ygh);  cudaGetSymbolAddress((void**)&ygl, g_ygl);
    cudaGetSymbolAddress((void**)&ymh,  g_ymh);  cudaGetSymbolAddress((void**)&yml, g_yml);
    cudaGetSymbolAddress((void**)&wH,   g_wH);   cudaGetSymbolAddress((void**)&wL,  g_wL);

    const size_t SDI  = (size_t)NTOK * DI;
    const size_t SDI2 = (size_t)NTOK * DI2;
    const size_t SXD  = (size_t)NTOK * XD;
    const int MB = NTOK / 128;
    const int CONV_GRID = NTOK * DI / 4 / 256;

    const size_t SZ_IN   = (size_t)DI2 * DMODEL;
    const size_t SZ_PIN  = (size_t)DI2 * DI;
    const size_t SZ_XP   = (size_t)XD * DI;
    const size_t SZ_DT   = (size_t)DI * DTR;
    const size_t SZ_POUT = (size_t)DI * DI;
    const size_t SZ_OUT  = (size_t)DMODEL * DI2;
    const size_t OFF_IN    = 0;
    const size_t OFF_P0IN  = OFF_IN + SZ_IN;
    const size_t OFF_P1IN  = OFF_P0IN + SZ_PIN;
    const size_t OFF_P0XP  = OFF_P1IN + SZ_PIN;
    const size_t OFF_P1XP  = OFF_P0XP + SZ_XP;
    const size_t OFF_P0DT  = OFF_P1XP + SZ_XP;
    const size_t OFF_P1DT  = OFF_P0DT + SZ_DT;
    const size_t OFF_P0OUT = OFF_P1DT + SZ_DT;
    const size_t OFF_P1OUT = OFF_P0OUT + SZ_POUT;
    const size_t OFF_OUT   = OFF_P1OUT + SZ_POUT;

    // 0: LN -> split xn
    ln_kernel<<<NTOK, 128>>>(x, norm_g, norm_b, xnh, xnl);

    // 1: split in_w
    split_kernel<<<(int)(SZ_IN / 4 / 256), 256>>>(in_w, wH + OFF_IN, wL + OFF_IN,
                                                  (int)(SZ_IN / 4));
    // 2: xp = xn @ in_w^T  (N=2048 -> 8 n-blocks)
    gemm5<0><<<dim3(8, MB, 1), 128, SM_TOT>>>(
        xnh, xnl, DMODEL, 0, wH + OFF_IN, wL + OFF_IN, 0, xp, 0, DI2, DMODEL,
        nullptr, nullptr, nullptr, nullptr, 0);

    // 3: xa = silu(causal dwconv(xp[:, :DI])) -> split only
    conv_silu_kernel<<<dim3(CONV_GRID, 1, 1), 256>>>(
        xp, DI2, 0, conv_w, conv_w, conv_b, conv_b, nullptr, 0, xah, xal, 0);

    // 4: split all remaining weights
    {
        SplitJobs j;
        j.src[0] = P[0][0]; j.off[0] = OFF_P0IN;  j.n4[0] = (int)(SZ_PIN / 4);
        j.src[1] = P[1][0]; j.off[1] = OFF_P1IN;  j.n4[1] = (int)(SZ_PIN / 4);
        j.src[2] = P[0][3]; j.off[2] = OFF_P0XP;  j.n4[2] = (int)(SZ_XP / 4);
        j.src[3] = P[1][3]; j.off[3] = OFF_P1XP;  j.n4[3] = (int)(SZ_XP / 4);
        j.src[4] = P[0][4]; j.off[4] = OFF_P0DT;  j.n4[4] = (int)(SZ_DT / 4);
        j.src[5] = P[1][4]; j.off[5] = OFF_P1DT;  j.n4[5] = (int)(SZ_DT / 4);
        j.src[6] = P[0][8]; j.off[6] = OFF_P0OUT; j.n4[6] = (int)(SZ_POUT / 4);
        j.src[7] = P[1][8]; j.off[7] = OFF_P1OUT; j.n4[7] = (int)(SZ_POUT / 4);
        j.src[8] = out_w;   j.off[8] = OFF_OUT;   j.n4[8] = (int)(SZ_OUT / 4);
        split_many<<<dim3((int)(SZ_PIN / 4 / 256), 9), 256>>>(j, wH, wL);
    }

    // 5: xz[p] = xa @ P[p].in_w^T  (N=2048 -> 8 n-blocks, z=2)
    gemm5<0><<<dim3(8, MB, 2), 128, SM_TOT>>>(
        xah, xal, DI, 0, wH + OFF_P0IN, wL + OFF_P0IN, SZ_PIN, xz, SDI2, DI2, DI,
        nullptr, nullptr, nullptr, nullptr, 0);

    // 6: xm[p] = silu(dwconv_p(xz[p][:, :DI])) -> fp32 + split
    conv_silu_kernel<<<dim3(CONV_GRID, 1, 2), 256>>>(
        xz, DI2, SDI2, P[0][1], P[1][1], P[0][2], P[1][2], xma, SDI, xmh, xml, SDI);

    // 7: xdbl[p] = xm[p] @ xp_w^T -> fp32 + split (N=96 -> 1 n-block)
    gemm5<3><<<dim3(1, MB, 2), 128, SM_TOT>>>(
        xmh, xml, DI, SDI, wH + OFF_P0XP, wL + OFF_P0XP, SZ_XP, xdbl, SXD, XD, DI,
        nullptr, nullptr, xdh, xdl, SXD);

    // 8: dt[p] = softplus(xdbl[p][:, :64] @ dt_w^T + dt_b)  (N=1024 -> 4 n-blocks)
    gemm5<1><<<dim3(4, MB, 2), 128, SM_TOT>>>(
        xdh, xdl, XD, SXD, wH + OFF_P0DT, wL + OFF_P0DT, SZ_DT, dtb, SDI, DI, DTR,
        P[0][5], P[1][5], nullptr, nullptr, 0);

    // 9: scan[p] + fused y*silu(z) -> split yg[p]
    scan_kernel<<<dim3(BN_ * (DI/16), 1, 2), 256>>>(
        xma, SDI, dtb, SDI, xdbl, SXD, xz, SDI2,
        P[0][6], P[1][6], P[0][7], P[1][7], ygh, ygl, SDI);

    // 10: ym[:, z*DI : z*DI+DI] = (yg[p] @ out_w^T) * silu(xp[:, DI:]) -> split direct
    gemm5<4><<<dim3(4, MB, 2), 128, SM_TOT>>>(
        ygh, ygl, DI, SDI, wH + OFF_P0OUT, wL + OFF_P0OUT, SZ_POUT, dtb, 0, DI, DI,
        xp, xp, ymh, yml, DI);

    // 11: out = ym @ out_w^T + x  (N=512 -> 2 n-blocks)
    gemm5<2><<<dim3(2, MB, 1), 128, SM_TOT>>>(
        ymh, yml, DI2, 0, wH + OFF_OUT, wL + OFF_OUT, 0, (float*)d_out, 0, DMODEL, DI2,
        x, nullptr, nullptr, nullptr, 0);
}

// round 16
// speedup vs baseline: 1.0464x; 1.0464x over previous
#include <cuda_runtime.h>
#include <cuda_bf16.h>
#include <math.h>
#include <stdint.h>

#define BN_    4
#define LL     2048
#define DMODEL 512
#define DI     1024
#define DI2    2048
#define DST    16
#define DTR    64
#define XD     96
#define NTOK   8192   // B * L

// tcgen05 only exists on the arch-specific target (sm_103a / sm_100a).
#if defined(__CUDA_ARCH_FEAT_SM103_ALL) || defined(__CUDA_ARCH_FEAT_SM100_ALL)
#define HAS_TC5 1
#endif

typedef __nv_bfloat16 bf16;

// ---------------- scratch (device globals: no allocation allowed) ----------------
__device__ float g_xp  [(size_t)NTOK * DI2];
__device__ float g_xz  [2][(size_t)NTOK * DI2];
__device__ float g_xma [2][(size_t)NTOK * DI];
__device__ float g_xdbl[2][(size_t)NTOK * XD];
__device__ float g_dt  [2][(size_t)NTOK * DI];
// bf16 hi/lo pre-split GEMM operands
__device__ bf16 g_xnh[(size_t)NTOK * DMODEL], g_xnl[(size_t)NTOK * DMODEL];
__device__ bf16 g_xah[(size_t)NTOK * DI],     g_xal[(size_t)NTOK * DI];
__device__ bf16 g_xmh[2][(size_t)NTOK * DI],  g_xml[2][(size_t)NTOK * DI];
__device__ bf16 g_xdh[2][(size_t)NTOK * XD],  g_xdl[2][(size_t)NTOK * XD];
__device__ bf16 g_ygh[2][(size_t)NTOK * DI],  g_ygl[2][(size_t)NTOK * DI];
__device__ bf16 g_ymh[(size_t)NTOK * DI2],    g_yml[(size_t)NTOK * DI2];
// all weights pre-split once, persistent slots (8,716,288 elems)
#define WTOT 8716288
__device__ bf16 g_wH[WTOT], g_wL[WTOT];

__device__ __forceinline__ float siluf(float x)     { return x / (1.f + __expf(-x)); }
__device__ __forceinline__ float softplusf(float x) { return x > 20.f ? x : log1pf(__expf(x)); }

__device__ __forceinline__ uint32_t pack_bf16x2(float x, float y) {
    uint32_t r;
    asm("cvt.rn.bf16x2.f32 %0, %1, %2;" : "=r"(r) : "f"(y), "f"(x));  // {lo=x, hi=y}
    return r;
}
__device__ __forceinline__ void split2(float x, float y, uint32_t& h, uint32_t& l) {
    h = pack_bf16x2(x, y);
    const float rx = __uint_as_float(h << 16);
    const float ry = __uint_as_float(h & 0xffff0000u);
    l = pack_bf16x2(x - rx, y - ry);
}

// ---------------- weight split kernels ----------------
__global__ void split_kernel(const float* __restrict__ in, bf16* __restrict__ hi,
                             bf16* __restrict__ lo, int n4)
{
    const int i = blockIdx.x * 256 + threadIdx.x;
    if (i < n4) {
        const float4 v = ((const float4*)in)[i];
        uint32_t h0, l0, h1, l1;
        split2(v.x, v.y, h0, l0);
        split2(v.z, v.w, h1, l1);
        ((uint2*)hi)[i] = make_uint2(h0, h1);
        ((uint2*)lo)[i] = make_uint2(l0, l1);
    }
}

struct SplitJobs {
    const float* src[9];
    size_t off[9];
    int n4[9];
};

__global__ void split_many(SplitJobs j, bf16* __restrict__ hi, bf16* __restrict__ lo)
{
    const int job = blockIdx.y;
    const int i = blockIdx.x * 256 + threadIdx.x;
    if (i < j.n4[job]) {
        const float4 v = ((const float4*)j.src[job])[i];
        uint32_t h0, l0, h1, l1;
        split2(v.x, v.y, h0, l0);
        split2(v.z, v.w, h1, l1);
        ((uint2*)(hi + j.off[job]))[i] = make_uint2(h0, h1);
        ((uint2*)(lo + j.off[job]))[i] = make_uint2(l0, l1);
    }
}

// ---------------- LayerNorm -> split bf16 ----------------
__global__ void ln_kernel(const float* __restrict__ x, const float* __restrict__ gg,
                          const float* __restrict__ bb,
                          bf16* __restrict__ hi, bf16* __restrict__ lo)
{
    __shared__ float red[8];
    const int row = blockIdx.x;
    const int t   = threadIdx.x;
    float4 v = ((const float4*)(x + (size_t)row * DMODEL))[t];
    float s = v.x + v.y + v.z + v.w;
#pragma unroll
    for (int o = 16; o; o >>= 1) s += __shfl_xor_sync(0xffffffffu, s, o);
    if ((t & 31) == 0) red[t >> 5] = s;
    __syncthreads();
    const float mu = (red[0] + red[1] + red[2] + red[3]) * (1.f / DMODEL);
    const float dx = v.x - mu, dy = v.y - mu, dz = v.z - mu, dw = v.w - mu;
    float vs = dx*dx + dy*dy + dz*dz + dw*dw;
#pragma unroll
    for (int o = 16; o; o >>= 1) vs += __shfl_xor_sync(0xffffffffu, vs, o);
    if ((t & 31) == 0) red[4 + (t >> 5)] = vs;
    __syncthreads();
    const float var = (red[4] + red[5] + red[6] + red[7]) * (1.f / DMODEL);
    const float inv = rsqrtf(var + 1e-5f);
    const int i0 = t << 2;
    float ox = dx * inv * gg[i0+0] + bb[i0+0];
    float oy = dy * inv * gg[i0+1] + bb[i0+1];
    float oz = dz * inv * gg[i0+2] + bb[i0+2];
    float ow = dw * inv * gg[i0+3] + bb[i0+3];
    uint32_t h0, l0, h1, l1;
    split2(ox, oy, h0, l0);
    split2(oz, ow, h1, l1);
    ((uint2*)(hi + (size_t)row * DMODEL))[t] = make_uint2(h0, h1);
    ((uint2*)(lo + (size_t)row * DMODEL))[t] = make_uint2(l0, l1);
}

#ifdef HAS_TC5
// ---------------- tcgen05 helpers ----------------
__device__ __forceinline__ uint32_t smem_u32(const void* p) {
    uint32_t a;
    asm("{ .reg .u64 t; cvta.to.shared.u64 t, %1; cvt.u32.u64 %0, t; }" : "=r"(a) : "l"(p));
    return a;
}
__device__ __forceinline__ uint32_t elect1() {
    uint32_t p;
    asm volatile("{\n\t.reg .pred p;\n\telect.sync _|p, 0xFFFFFFFF;\n\tselp.b32 %0, 1, 0, p;\n\t}"
                 : "=r"(p));
    return p;
}
__device__ __forceinline__ uint32_t swz(uint32_t off) { return off ^ ((off >> 3) & 0x70); }

__device__ __forceinline__ void cp16(uint32_t dst, const void* src, int sz) {
    asm volatile("cp.async.cg.shared.global [%0], [%1], 16, %2;"
                 :: "r"(dst), "l"(src), "r"(sz) : "memory");
}

// SW128 K-major smem descriptor (Blackwell): layout=2, version=1, SBO=64, LBO=1
static __device__ __forceinline__ uint64_t mkdesc(uint32_t addr) {
    const uint64_t base = (2ull << 61) | (1ull << 46) | (64ull << 32) | (1ull << 16);
    return base | ((addr >> 4) & 0x3FFFu);
}

__device__ __forceinline__ void mma_f16_ss(uint32_t d, uint64_t a, uint64_t b,
                                           uint32_t idesc, uint32_t en) {
    asm volatile(
        "{\n\t.reg .pred p;\n\tsetp.ne.u32 p, %4, 0;\n\t"
        "tcgen05.mma.cta_group::1.kind::f16 [%0], %1, %2, %3, {%5,%5,%5,%5}, p;\n\t}"
        :: "r"(d), "l"(a), "l"(b), "r"(idesc), "r"(en), "r"(0u) : "memory");
}

__device__ __forceinline__ void mbar_wait(uint32_t mbar, uint32_t parity) {
    asm volatile(
        "{\n\t.reg .pred P;\n\t"
        "W_%=:\n\t"
        "mbarrier.try_wait.parity.acquire.cta.shared::cta.b64 P, [%0], %1, 0x989680;\n\t"
        "@P bra.uni D_%=;\n\t"
        "bra.uni W_%=;\n\t"
        "D_%=:\n\t}"
        :: "r"(mbar), "r"(parity) : "memory");
}

#define TC_LD32(r, addr) \
    asm volatile( \
        "tcgen05.ld.sync.aligned.32x32b.x32.b32 " \
        "{%0, %1, %2, %3, %4, %5, %6, %7, " \
        " %8, %9, %10, %11, %12, %13, %14, %15, " \
        " %16, %17, %18, %19, %20, %21, %22, %23, " \
        " %24, %25, %26, %27, %28, %29, %30, %31}, [%32];" \
        : "=r"((r)[0]),  "=r"((r)[1]),  "=r"((r)[2]),  "=r"((r)[3]), \
          "=r"((r)[4]),  "=r"((r)[5]),  "=r"((r)[6]),  "=r"((r)[7]), \
          "=r"((r)[8]),  "=r"((r)[9]),  "=r"((r)[10]), "=r"((r)[11]), \
          "=r"((r)[12]), "=r"((r)[13]), "=r"((r)[14]), "=r"((r)[15]), \
          "=r"((r)[16]), "=r"((r)[17]), "=r"((r)[18]), "=r"((r)[19]), \
          "=r"((r)[20]), "=r"((r)[21]), "=r"((r)[22]), "=r"((r)[23]), \
          "=r"((r)[24]), "=r"((r)[25]), "=r"((r)[26]), "=r"((r)[27]), \
          "=r"((r)[28]), "=r"((r)[29]), "=r"((r)[30]), "=r"((r)[31]) \
        : "r"(addr))
#else
__device__ __forceinline__ void mma_bf16(float* c, const uint32_t* a, const uint32_t* b) {
    asm volatile("mma.sync.aligned.m16n8k16.row.col.f32.bf16.bf16.f32 "
        "{%0,%1,%2,%3}, {%4,%5,%6,%7}, {%8,%9}, {%0,%1,%2,%3};"
        : "+f"(c[0]), "+f"(c[1]), "+f"(c[2]), "+f"(c[3])
        : "r"(a[0]), "r"(a[1]), "r"(a[2]), "r"(a[3]), "r"(b[0]), "r"(b[1]));
}
#endif

// ---------------- GEMM: C[M,N] = (Ah+Al)[M,K] @ (Wh+Wl)[N,K]^T, 3-pass split -------
// R13-proven: 128x128 tiles, BK=64 single-stage, cp.async fills, 66.5KB -> 3 CTAs/SM.
// gridDim.z batches directions. M mult of 128, K mult of 64 (fallback: 16).
// EPI: 0 none, 1 softplus(acc+aux[n]), 2 acc+aux[m*N+n], 3 fp32 C + split (Ch,Cl),
//      4 gated split:  split(acc * silu(aux[m*DI2+DI+col])) -> Ch/Cl at [m*DI2+col]
//        (Ch/Cl pre-shifted by z*chStrideZ; no fp32 C write)
#define SM_TOT (1024 + 65536)   // hdr + 4 tiles x 16KB

template<int EPI>
__global__ void __launch_bounds__(128)
gemm5(const bf16* __restrict__ Ah, const bf16* __restrict__ Al, int lda, size_t aStrideZ,
      const bf16* __restrict__ Wh, const bf16* __restrict__ Wl, size_t wStrideZ,
      float* __restrict__ C, size_t cStrideZ, int N, int K,
      const float* __restrict__ aux0, const float* __restrict__ aux1,
      bf16* __restrict__ Ch, bf16* __restrict__ Cl, size_t chStrideZ)
{
    const int z = blockIdx.z;
    Ah += (size_t)z * aStrideZ;  Al += (size_t)z * aStrideZ;
    Wh += (size_t)z * wStrideZ;  Wl += (size_t)z * wStrideZ;
    C  += (size_t)z * cStrideZ;
    const float* aux = z ? aux1 : aux0;
    if (EPI >= 3) { Ch += (size_t)z * chStrideZ; Cl += (size_t)z * chStrideZ; }

#ifdef HAS_TC5
    // ================= tcgen05 path (sm_103a SASS), single-stage BK=64 =============
    extern __shared__ __align__(1024) char sm[];
    const uint32_t sb = smem_u32(sm);
    const int tid = threadIdx.x, warp = tid >> 5, lane = tid & 31;
    const int m0 = blockIdx.y << 7, n0 = blockIdx.x << 7;

    if (warp == 0) {
        asm volatile("tcgen05.alloc.cta_group::1.sync.aligned.shared::cta.b32 [%0], %1;"
                     :: "r"(sb), "r"(128u) : "memory");
        asm volatile("tcgen05.relinquish_alloc_permit.cta_group::1.sync.aligned;");
    }
    if (tid == 0)
        asm volatile("mbarrier.init.shared.b64 [%0], %1;" :: "r"(sb + 8), "r"(1u) : "memory");
    __syncthreads();
    uint32_t tmem;
    asm volatile("ld.shared.b32 %0, [%1];" : "=r"(tmem) : "r"(sb));

    const uint32_t idesc = 0x8200490u;   // M=128, N=128, bf16 x bf16 -> f32
    uint32_t phase = 0;

    for (int k0 = 0; k0 < K; k0 += 64) {
        // fill: async 16B copies into SW128-swizzled tiles
#pragma unroll
        for (int i = 0; i < 8; i++) {
            const int idx = tid + (i << 7);          // 0..1023
            const int r   = idx >> 3;                // row 0..127
            const int ch  = idx & 7;                 // 16B chunk (8 bf16)
            const uint32_t sw = swz((uint32_t)(r * 128 + ch * 16));
            const size_t aoff = (size_t)(m0 + r) * lda + k0 + (ch << 3);
            cp16(sb + 1024 + 0     + sw, Ah + aoff, 16);
            cp16(sb + 1024 + 16384 + sw, Al + aoff, 16);
            const int rb  = (n0 + r < N) ? (n0 + r) : 0;
            const int bsz = (n0 + r < N) ? 16 : 0;
            const size_t boff = (size_t)rb * K + k0 + (ch << 3);
            cp16(sb + 1024 + 32768 + sw, Wh + boff, bsz);
            cp16(sb + 1024 + 49152 + sw, Wl + boff, bsz);
        }
        asm volatile("cp.async.commit_group;" ::: "memory");
        asm volatile("cp.async.wait_group 0;" ::: "memory");
        asm volatile("fence.proxy.async.shared::cta;" ::: "memory");
        __syncthreads();

        if (warp == 0 && elect1()) {
            const uint64_t ah = mkdesc(sb + 1024),         al = mkdesc(sb + 1024 + 16384);
            const uint64_t bh = mkdesc(sb + 1024 + 32768), bl = mkdesc(sb + 1024 + 49152);
#pragma unroll
            for (int kc = 0; kc < 4; kc++) {
                mma_f16_ss(tmem, ah + kc * 2, bh + kc * 2, idesc, (k0 | kc) != 0);
                mma_f16_ss(tmem, ah + kc * 2, bl + kc * 2, idesc, 1u);
                mma_f16_ss(tmem, al + kc * 2, bh + kc * 2, idesc, 1u);
            }
            asm volatile(
                "tcgen05.commit.cta_group::1.mbarrier::arrive::one.shared::cluster.b64 [%0];"
                :: "r"(sb + 8) : "memory");
        }
        mbar_wait(sb + 8, phase);
        phase ^= 1;
    }

    asm volatile("tcgen05.fence::after_thread_sync;" ::: "memory");

    const int m = m0 + warp * 32 + lane;
#pragma unroll
    for (int base = 0; base < 128; base += 32) {
        uint32_t r[32];
        TC_LD32(r, tmem + base);
        asm volatile("tcgen05.wait::ld.sync.aligned;" ::: "memory");
#pragma unroll
        for (int j = 0; j < 32; j += 4) {
            const int col = n0 + base + j;
            if (col < N) {
                float4 v = make_float4(__uint_as_float(r[j]),   __uint_as_float(r[j+1]),
                                       __uint_as_float(r[j+2]), __uint_as_float(r[j+3]));
                if (EPI == 1) {
                    const float4 b = *(const float4*)(aux + col);
                    v.x = softplusf(v.x + b.x); v.y = softplusf(v.y + b.y);
                    v.z = softplusf(v.z + b.z); v.w = softplusf(v.w + b.w);
                }
                if (EPI == 2) {
                    const float4 a4 = *(const float4*)(aux + (size_t)m * N + col);
                    v.x += a4.x; v.y += a4.y; v.z += a4.z; v.w += a4.w;
                }
                if (EPI == 4) {
                    const float4 g4 = *(const float4*)(aux + (size_t)m * DI2 + DI + col);
                    v.x *= siluf(g4.x); v.y *= siluf(g4.y);
                    v.z *= siluf(g4.z); v.w *= siluf(g4.w);
                    uint32_t h0, l0, h1, l1;
                    split2(v.x, v.y, h0, l0);
                    split2(v.z, v.w, h1, l1);
                    *(uint2*)(Ch + (size_t)m * DI2 + col) = make_uint2(h0, h1);
                    *(uint2*)(Cl + (size_t)m * DI2 + col) = make_uint2(l0, l1);
                } else {
                    *(float4*)(C + (size_t)m * N + col) = v;
                    if (EPI == 3) {
                        uint32_t h0, l0, h1, l1;
                        split2(v.x, v.y, h0, l0);
                        split2(v.z, v.w, h1, l1);
                        *(uint2*)(Ch + (size_t)m * N + col) = make_uint2(h0, h1);
                        *(uint2*)(Cl + (size_t)m * N + col) = make_uint2(l0, l1);
                    }
                }
            }
        }
    }

    __syncthreads();
    if (tid == 0)
        asm volatile("mbarrier.inval.shared.b64 [%0];" :: "r"(sb + 8) : "memory");
    __syncthreads();
    if (warp == 0)
        asm volatile("tcgen05.dealloc.cta_group::1.sync.aligned.b32 %0, %1;"
                     :: "r"(tmem), "r"(128u));
#else
    // ================= mma.sync fallback (compile-only for non-'a' pass) ============
    __shared__ uint32_t sAh[8][136], sAl[8][136], sBh[8][136], sBl[8][136];
    const int tid  = threadIdx.x;
    const int m0   = blockIdx.y << 7;
    const int n0   = blockIdx.x << 7;
    const int lane = tid & 31, warp = tid >> 5;
    const int wm = (warp >> 1) << 6, wn = (warp & 1) << 6;
    const int g  = lane >> 2,  t  = lane & 3;

    float acc[4][8][4];
#pragma unroll
    for (int i = 0; i < 4; i++)
#pragma unroll
        for (int j = 0; j < 8; j++)
#pragma unroll
            for (int q = 0; q < 4; q++) acc[i][j][q] = 0.f;

#pragma unroll 1
    for (int k0 = 0; k0 < K; k0 += 16) {
#pragma unroll
        for (int i = 0; i < 8; i++) {
            const int idx = tid + (i << 7);
            const int r   = idx >> 3;
            const int k2  = idx & 7;
            sAh[k2][r] = *(const uint32_t*)(Ah + (size_t)(m0 + r) * lda + k0 + k2 * 2);
            sAl[k2][r] = *(const uint32_t*)(Al + (size_t)(m0 + r) * lda + k0 + k2 * 2);
            uint32_t bh = 0, bl = 0;
            if (n0 + r < N) {
                bh = *(const uint32_t*)(Wh + (size_t)(n0 + r) * K + k0 + k2 * 2);
                bl = *(const uint32_t*)(Wl + (size_t)(n0 + r) * K + k0 + k2 * 2);
            }
            sBh[k2][r] = bh; sBl[k2][r] = bl;
        }
        __syncthreads();

        uint32_t bh[8][2], bl[8][2];
#pragma unroll
        for (int nt = 0; nt < 8; nt++) {
            const int nb = wn + (nt << 3) + g;
            bh[nt][0] = sBh[t][nb];     bh[nt][1] = sBh[t+4][nb];
            bl[nt][0] = sBl[t][nb];     bl[nt][1] = sBl[t+4][nb];
        }
#pragma unroll
        for (int mt = 0; mt < 4; mt++) {
            const int mb = wm + (mt << 4) + g;
            uint32_t ah[4] = { sAh[t][mb], sAh[t][mb+8], sAh[t+4][mb], sAh[t+4][mb+8] };
            uint32_t al[4] = { sAl[t][mb], sAl[t][mb+8], sAl[t+4][mb], sAl[t+4][mb+8] };
#pragma unroll
            for (int nt = 0; nt < 8; nt++) {
                mma_bf16(acc[mt][nt], ah, bh[nt]);
                mma_bf16(acc[mt][nt], ah, bl[nt]);
                mma_bf16(acc[mt][nt], al, bh[nt]);
            }
        }
        __syncthreads();
    }

#pragma unroll
    for (int mt = 0; mt < 4; mt++) {
        const int r0 = m0 + wm + (mt << 4) + g;
#pragma unroll
        for (int nt = 0; nt < 8; nt++) {
            const int col = n0 + wn + (nt << 3) + (t << 1);
            if (col < N) {
                float v0 = acc[mt][nt][0], v1 = acc[mt][nt][1];
                float v2 = acc[mt][nt][2], v3 = acc[mt][nt][3];
                if (EPI == 1) {
                    const float b0 = __ldg(&aux[col]), b1 = __ldg(&aux[col+1]);
                    v0 = softplusf(v0 + b0); v1 = softplusf(v1 + b1);
                    v2 = softplusf(v2 + b0); v3 = softplusf(v3 + b1);
                }
                if (EPI == 2) {
                    const float2 a0 = *(const float2*)(aux + (size_t)r0 * N + col);
                    const float2 a1 = *(const float2*)(aux + (size_t)(r0+8) * N + col);
                    v0 += a0.x; v1 += a0.y; v2 += a1.x; v3 += a1.y;
                }
                if (EPI == 4) {
                    const float2 g0 = *(const float2*)(aux + (size_t)r0 * DI2 + DI + col);
                    const float2 g1 = *(const float2*)(aux + (size_t)(r0+8) * DI2 + DI + col);
                    v0 *= siluf(g0.x); v1 *= siluf(g0.y);
                    v2 *= siluf(g1.x); v3 *= siluf(g1.y);
                    uint32_t h, l;
                    split2(v0, v1, h, l);
                    *(uint32_t*)(Ch + (size_t)r0 * DI2 + col) = h;
                    *(uint32_t*)(Cl + (size_t)r0 * DI2 + col) = l;
                    split2(v2, v3, h, l);
                    *(uint32_t*)(Ch + (size_t)(r0+8) * DI2 + col) = h;
                    *(uint32_t*)(Cl + (size_t)(r0+8) * DI2 + col) = l;
                } else {
                    *(float2*)(C + (size_t)r0     * N + col) = make_float2(v0, v1);
                    *(float2*)(C + (size_t)(r0+8) * N + col) = make_float2(v2, v3);
                    if (EPI == 3) {
                        uint32_t h, l;
                        split2(v0, v1, h, l);
                        *(uint32_t*)(Ch + (size_t)r0 * N + col) = h;
                        *(uint32_t*)(Cl + (size_t)r0 * N + col) = l;
                        split2(v2, v3, h, l);
                        *(uint32_t*)(Ch + (size_t)(r0+8) * N + col) = h;
                        *(uint32_t*)(Cl + (size_t)(r0+8) * N + col) = l;
                    }
                }
            }
        }
    }
#endif
}

// ---------------- depthwise conv (K=4) + SiLU + split, float4, z = direction -------
__global__ void conv_silu_kernel(const float* __restrict__ in, int ldin, size_t inStrideZ,
                                 const float* __restrict__ w0, const float* __restrict__ w1,
                                 const float* __restrict__ b0, const float* __restrict__ b1,
                                 float* __restrict__ outf, size_t outfStrideZ,
                                 bf16* __restrict__ outh, bf16* __restrict__ outl,
                                 size_t outStrideZ)
{
    const int z = blockIdx.z;
    const float* inp  = in + (size_t)z * inStrideZ;
    const float* w    = z ? w1 : w0;
    const float* bias = z ? b1 : b0;
    bf16* oh = outh + (size_t)z * outStrideZ;
    bf16* ol = outl + (size_t)z * outStrideZ;

    const int idx4 = blockIdx.x * 256 + threadIdx.x;
    const int dq   = idx4 & (DI / 4 - 1);
    const int tok  = idx4 >> 8;
    const int l    = tok & (LL - 1);
    const int dd   = dq << 2;
    const float* base = inp + (size_t)(tok - l) * ldin + dd;

    float wr[4][4];
    *(float4*)wr[0] = *(const float4*)(w + (dd+0)*4);
    *(float4*)wr[1] = *(const float4*)(w + (dd+1)*4);
    *(float4*)wr[2] = *(const float4*)(w + (dd+2)*4);
    *(float4*)wr[3] = *(const float4*)(w + (dd+3)*4);
    float4 acc = *(const float4*)(bias + dd);

    if (!z) {
#pragma unroll
        for (int k = 0; k < 4; k++) {
            const int ls = l - 3 + k;
            if (ls >= 0) {
                const float4 v = *(const float4*)(base + (size_t)ls * ldin);
                acc.x = fmaf(v.x, wr[0][k], acc.x);
                acc.y = fmaf(v.y, wr[1][k], acc.y);
                acc.z = fmaf(v.z, wr[2][k], acc.z);
                acc.w = fmaf(v.w, wr[3][k], acc.w);
            }
        }
    } else {
#pragma unroll
        for (int j = 0; j < 4; j++) {
            const int ls = l + j;
            if (ls < LL) {
                const float4 v = *(const float4*)(base + (size_t)ls * ldin);
                acc.x = fmaf(v.x, wr[0][3-j], acc.x);
                acc.y = fmaf(v.y, wr[1][3-j], acc.y);
                acc.z = fmaf(v.z, wr[2][3-j], acc.z);
                acc.w = fmaf(v.w, wr[3][3-j], acc.w);
            }
        }
    }
    float4 s = make_float4(siluf(acc.x), siluf(acc.y), siluf(acc.z), siluf(acc.w));
    if (outf) ((float4*)(outf + (size_t)z * outfStrideZ))[idx4] = s;
    uint32_t h0, l0, h1, l1;
    split2(s.x, s.y, h0, l0);
    split2(s.z, s.w, h1, l1);
    ((uint2*)oh)[idx4] = make_uint2(h0, h1);
    ((uint2*)ol)[idx4] = make_uint2(l0, l1);
}

// ---------------- selective scan + fused gating, z = direction ----------------
__global__ __launch_bounds__(256) void scan_kernel(
    const float* __restrict__ u, size_t uStrideZ,
    const float* __restrict__ dt, size_t dtStrideZ,
    const float* __restrict__ xdbl, size_t xdStrideZ,
    const float* __restrict__ xz, size_t xzStrideZ,
    const float* __restrict__ Alog0, const float* __restrict__ Alog1,
    const float* __restrict__ Dp0, const float* __restrict__ Dp1,
    bf16* __restrict__ ygh, bf16* __restrict__ ygl, size_t ygStrideZ)
{
    __shared__ float s_u[64][16], s_dt[64][16], s_B[64][16], s_C[64][16], s_y[64][16];
    const int z = blockIdx.z;
    const int backward = z;
    const float* up  = u + (size_t)z * uStrideZ;
    const float* dtp = dt + (size_t)z * dtStrideZ;
    const float* xdp = xdbl + (size_t)z * xdStrideZ;
    const float* xzp = xz + (size_t)z * xzStrideZ;
    const float* Alog = z ? Alog1 : Alog0;
    const float* Dp   = z ? Dp1   : Dp0;
    bf16* yh = ygh + (size_t)z * ygStrideZ;
    bf16* yl = ygl + (size_t)z * ygStrideZ;

    const int b     = blockIdx.x >> 6;
    const int dbase = (blockIdx.x & 63) << 4;
    const int tid = threadIdx.x;
    const int dl  = tid >> 4;
    const int n   = tid & 15;
    const int d   = dbase + dl;
    const float a    = -expf(Alog[d * DST + n]);
    const float Dloc = Dp[d];
    float h = 0.f;
    const size_t brow = (size_t)b * LL;

    for (int chunk = 0; chunk < LL / 64; chunk++) {
        const int c0 = chunk << 6;
#pragma unroll
        for (int i = 0; i < 4; i++) {
            const int ii = tid + (i << 8);
            const int tt = ii >> 4, dc = ii & 15;
            const int t = c0 + tt;
            const int l = backward ? (LL - 1 - t) : t;
            const size_t roff = brow + l;
            s_u [tt][dc] = up [roff * DI + dbase + dc];
            s_dt[tt][dc] = dtp[roff * DI + dbase + dc];
            s_B [tt][dc] = xdp[roff * XD + 64 + dc];
            s_C [tt][dc] = xdp[roff * XD + 80 + dc];
        }
        __syncthreads();
#pragma unroll 8
        for (int tt = 0; tt < 64; tt++) {
            const float dtv = s_dt[tt][dl];
            const float uv  = s_u [tt][dl];
            const float dA  = __expf(dtv * a);
            const float db  = dtv * uv * s_B[tt][n];
            h = fmaf(dA, h, db);
            float yp = h * s_C[tt][n];
            yp += __shfl_xor_sync(0xffffffffu, yp, 8);
            yp += __shfl_xor_sync(0xffffffffu, yp, 4);
            yp += __shfl_xor_sync(0xffffffffu, yp, 2);
            yp += __shfl_xor_sync(0xffffffffu, yp, 1);
            if (n == 0) s_y[tt][dl] = fmaf(uv, Dloc, yp);
        }
        __syncthreads();
#pragma unroll
        for (int i = 0; i < 4; i++) {
            const int ii = tid + (i << 8);
            const int tt = ii >> 4, dc = ii & 15;
            const int t = c0 + tt;
            const int l = backward ? (LL - 1 - t) : t;
            const size_t roff = brow + l;
            const float zz = xzp[roff * DI2 + DI + dbase + dc];
            const float v = s_y[tt][dc] * siluf(zz);
            const bf16 hv = __float2bfloat16(v);
            yh[roff * DI + dbase + dc] = hv;
            yl[roff * DI + dbase + dc] = __float2bfloat16(v - __bfloat162float(hv));
        }
        __syncthreads();
    }
}

// ---------------- host ----------------
extern "C" void kernel_launch(void* const* d_in, const int* in_sizes, int n_in,
                              void* d_out, int out_size)
{
    const float* x      = (const float*)d_in[0];
    const float* norm_g = (const float*)d_in[1];
    const float* norm_b = (const float*)d_in[2];
    const float* in_w   = (const float*)d_in[3];
    const float* conv_w = (const float*)d_in[4];
    const float* conv_b = (const float*)d_in[5];
    const float* out_w  = (const float*)d_in[6];
    const float* P[2][9];
    for (int p = 0; p < 2; p++)
        for (int i = 0; i < 9; i++)
            P[p][i] = (const float*)d_in[7 + p * 9 + i];
    // P[p]: 0 in_w, 1 conv_w, 2 conv_b, 3 xp_w, 4 dt_w, 5 dt_b, 6 Alog, 7 D, 8 out_w

    cudaFuncSetAttribute(gemm5<0>, cudaFuncAttributeMaxDynamicSharedMemorySize, SM_TOT);
    cudaFuncSetAttribute(gemm5<1>, cudaFuncAttributeMaxDynamicSharedMemorySize, SM_TOT);
    cudaFuncSetAttribute(gemm5<2>, cudaFuncAttributeMaxDynamicSharedMemorySize, SM_TOT);
    cudaFuncSetAttribute(gemm5<3>, cudaFuncAttributeMaxDynamicSharedMemorySize, SM_TOT);
    cudaFuncSetAttribute(gemm5<4>, cudaFuncAttributeMaxDynamicSharedMemorySize, SM_TOT);

    float *xp, *xz, *xma, *xdbl, *dtb;
    bf16 *xnh, *xnl, *xah, *xal, *xmh, *xml, *xdh, *xdl, *ygh, *ygl, *ymh, *yml, *wH, *wL;
    cudaGetSymbolAddress((void**)&xp,   g_xp);
    cudaGetSymbolAddress((void**)&xz,   g_xz);
    cudaGetSymbolAddress((void**)&xma,  g_xma);
    cudaGetSymbolAddress((void**)&xdbl, g_xdbl);
    cudaGetSymbolAddress((void**)&dtb,  g_dt);
    cudaGetSymbolAddress((void**)&xnh,  g_xnh);  cudaGetSymbolAddress((void**)&xnl, g_xnl);
    cudaGetSymbolAddress((void**)&xah,  g_xah);  cudaGetSymbolAddress((void**)&xal, g_xal);
    cudaGetSymbolAddress((void**)&xmh,  g_xmh);  cudaGetSymbolAddress((void**)&xml, g_xml);
    cudaGetSymbolAddress((void**)&xdh,  g_xdh);  cudaGetSymbolAddress((void**)&xdl, g_xdl);
    cudaGetSymbolAddress((void**)&ygh,  g_ygh);  cudaGetSymbolAddress((void**)&ygl, g_ygl);
    cudaGetSymbolAddress((void**)&ymh,  g_ymh);  cudaGetSymbolAddress((void**)&yml, g_yml);
    cudaGetSymbolAddress((void**)&wH,   g_wH);   cudaGetSymbolAddress((void**)&wL,  g_wL);

    const size_t SDI  = (size_t)NTOK * DI;
    const size_t SDI2 = (size_t)NTOK * DI2;
    const size_t SXD  = (size_t)NTOK * XD;
    const int MB = NTOK / 128;
    const int CONV_GRID = NTOK * DI / 4 / 256;

    const size_t SZ_IN   = (size_t)DI2 * DMODEL;
    const size_t SZ_PIN  = (size_t)DI2 * DI;
    const size_t SZ_XP   = (size_t)XD * DI;
    const size_t SZ_DT   = (size_t)DI * DTR;
    const size_t SZ_POUT = (size_t)DI * DI;
    const size_t SZ_OUT  = (size_t)DMODEL * DI2;
    const size_t OFF_IN    = 0;
    const size_t OFF_P0IN  = OFF_IN + SZ_IN;
    const size_t OFF_P1IN  = OFF_P0IN + SZ_PIN;
    const size_t OFF_P0XP  = OFF_P1IN + SZ_PIN;
    const size_t OFF_P1XP  = OFF_P0XP + SZ_XP;
    const size_t OFF_P0DT  = OFF_P1XP + SZ_XP;
    const size_t OFF_P1DT  = OFF_P0DT + SZ_DT;
    const size_t OFF_P0OUT = OFF_P1DT + SZ_DT;
    const size_t OFF_P1OUT = OFF_P0OUT + SZ_POUT;
    const size_t OFF_OUT   = OFF_P1OUT + SZ_POUT;

    // 0: LN -> split xn
    ln_kernel<<<NTOK, 128>>>(x, norm_g, norm_b, xnh, xnl);

    // 1: split in_w
    split_kernel<<<(int)(SZ_IN / 4 / 256), 256>>>(in_w, wH + OFF_IN, wL + OFF_IN,
                                                  (int)(SZ_IN / 4));
    // 2: xp = xn @ in_w^T
    gemm5<0><<<dim3(DI2/128, MB, 1), 128, SM_TOT>>>(
        xnh, xnl, DMODEL, 0, wH + OFF_IN, wL + OFF_IN, 0, xp, 0, DI2, DMODEL,
        nullptr, nullptr, nullptr, nullptr, 0);

    // 3: xa = silu(causal dwconv(xp[:, :DI])) -> split only
    conv_silu_kernel<<<dim3(CONV_GRID, 1, 1), 256>>>(
        xp, DI2, 0, conv_w, conv_w, conv_b, conv_b, nullptr, 0, xah, xal, 0);

    // 4: split all remaining weights (9 jobs, one launch)
    {
        SplitJobs j;
        j.src[0] = P[0][0]; j.off[0] = OFF_P0IN;  j.n4[0] = (int)(SZ_PIN / 4);
        j.src[1] = P[1][0]; j.off[1] = OFF_P1IN;  j.n4[1] = (int)(SZ_PIN / 4);
        j.src[2] = P[0][3]; j.off[2] = OFF_P0XP;  j.n4[2] = (int)(SZ_XP / 4);
        j.src[3] = P[1][3]; j.off[3] = OFF_P1XP;  j.n4[3] = (int)(SZ_XP / 4);
        j.src[4] = P[0][4]; j.off[4] = OFF_P0DT;  j.n4[4] = (int)(SZ_DT / 4);
        j.src[5] = P[1][4]; j.off[5] = OFF_P1DT;  j.n4[5] = (int)(SZ_DT / 4);
        j.src[6] = P[0][8]; j.off[6] = OFF_P0OUT; j.n4[6] = (int)(SZ_POUT / 4);
        j.src[7] = P[1][8]; j.off[7] = OFF_P1OUT; j.n4[7] = (int)(SZ_POUT / 4);
        j.src[8] = out_w;   j.off[8] = OFF_OUT;   j.n4[8] = (int)(SZ_OUT / 4);
        split_many<<<dim3((int)(SZ_PIN / 4 / 256), 9), 256>>>(j, wH, wL);
    }

    // 5: xz[p] = xa @ P[p].in_w^T, z = direction
    gemm5<0><<<dim3(DI2/128, MB, 2), 128, SM_TOT>>>(
        xah, xal, DI, 0, wH + OFF_P0IN, wL + OFF_P0IN, SZ_PIN, xz, SDI2, DI2, DI,
        nullptr, nullptr, nullptr, nullptr, 0);

    // 6: xm[p] = silu(dwconv_p(xz[p][:, :DI])) -> fp32 (scan u) + split
    conv_silu_kernel<<<dim3(CONV_GRID, 1, 2), 256>>>(
        xz, DI2, SDI2, P[0][1], P[1][1], P[0][2], P[1][2], xma, SDI, xmh, xml, SDI);

    // 7: xdbl[p] = xm[p] @ xp_w^T -> fp32 + split
    gemm5<3><<<dim3(1, MB, 2), 128, SM_TOT>>>(
        xmh, xml, DI, SDI, wH + OFF_P0XP, wL + OFF_P0XP, SZ_XP, xdbl, SXD, XD, DI,
        nullptr, nullptr, xdh, xdl, SXD);

    // 8: dt[p] = softplus(xdbl[p][:, :64] @ dt_w^T + dt_b)
    gemm5<1><<<dim3(DI/128, MB, 2), 128, SM_TOT>>>(
        xdh, xdl, XD, SXD, wH + OFF_P0DT, wL + OFF_P0DT, SZ_DT, dtb, SDI, DI, DTR,
        P[0][5], P[1][5], nullptr, nullptr, 0);

    // 9: scan[p] + fused y*silu(z) -> split yg[p]
    scan_kernel<<<dim3(BN_ * (DI/16), 1, 2), 256>>>(
        xma, SDI, dtb, SDI, xdbl, SXD, xz, SDI2,
        P[0][6], P[1][6], P[0][7], P[1][7], ygh, ygl, SDI);

    // 10: ym[:, z*DI : z*DI+DI] = (yg[p] @ out_w^T) * silu(xp[:, DI:]) -> split direct
    //     (fused ymix; C unused in EPI=4)
    gemm5<4><<<dim3(DI/128, MB, 2), 128, SM_TOT>>>(
        ygh, ygl, DI, SDI, wH + OFF_P0OUT, wL + OFF_P0OUT, SZ_POUT, dtb, 0, DI, DI,
        xp, xp, ymh, yml, DI);

    // 11: out = ym @ out_w^T + x
    gemm5<2><<<dim3(DMODEL/128, MB, 1), 128, SM_TOT>>>(
        ymh, yml, DI2, 0, wH + OFF_OUT, wL + OFF_OUT, 0, (float*)d_out, 0, DMODEL, DI2,
        x, nullptr, nullptr, nullptr, 0);
}

// round 17
// speedup vs baseline: 1.1124x; 1.0630x over previous
#include <cuda_runtime.h>
#include <cuda_bf16.h>
#include <math.h>
#include <stdint.h>

#define BN_    4
#define LL     2048
#define DMODEL 512
#define DI     1024
#define DI2    2048
#define DST    16
#define DTR    64
#define XD     96
#define NTOK   8192   // B * L

// tcgen05 only exists on the arch-specific target (sm_103a / sm_100a).
#if defined(__CUDA_ARCH_FEAT_SM103_ALL) || defined(__CUDA_ARCH_FEAT_SM100_ALL)
#define HAS_TC5 1
#endif

typedef __nv_bfloat16 bf16;

// ---------------- scratch (device globals: no allocation allowed) ----------------
__device__ float g_xp  [(size_t)NTOK * DI2];
__device__ float g_xz  [2][(size_t)NTOK * DI2];
__device__ float g_xma [2][(size_t)NTOK * DI];
__device__ float g_xdbl[2][(size_t)NTOK * XD];
__device__ float g_dt  [2][(size_t)NTOK * DI];   // mamba-out aliases this after scan
// bf16 hi/lo pre-split GEMM operands
__device__ bf16 g_xnh[(size_t)NTOK * DMODEL], g_xnl[(size_t)NTOK * DMODEL];
__device__ bf16 g_xah[(size_t)NTOK * DI],     g_xal[(size_t)NTOK * DI];
__device__ bf16 g_xmh[2][(size_t)NTOK * DI],  g_xml[2][(size_t)NTOK * DI];
__device__ bf16 g_xdh[2][(size_t)NTOK * XD],  g_xdl[2][(size_t)NTOK * XD];
__device__ bf16 g_ygh[2][(size_t)NTOK * DI],  g_ygl[2][(size_t)NTOK * DI];
__device__ bf16 g_ymh[(size_t)NTOK * DI2],    g_yml[(size_t)NTOK * DI2];
// all weights pre-split once, persistent slots (8,716,288 elems)
#define WTOT 8716288
__device__ bf16 g_wH[WTOT], g_wL[WTOT];

__device__ __forceinline__ float siluf(float x)     { return x / (1.f + __expf(-x)); }
__device__ __forceinline__ float softplusf(float x) { return x > 20.f ? x : log1pf(__expf(x)); }

__device__ __forceinline__ uint32_t pack_bf16x2(float x, float y) {
    uint32_t r;
    asm("cvt.rn.bf16x2.f32 %0, %1, %2;" : "=r"(r) : "f"(y), "f"(x));  // {lo=x, hi=y}
    return r;
}
__device__ __forceinline__ void split2(float x, float y, uint32_t& h, uint32_t& l) {
    h = pack_bf16x2(x, y);
    const float rx = __uint_as_float(h << 16);
    const float ry = __uint_as_float(h & 0xffff0000u);
    l = pack_bf16x2(x - rx, y - ry);
}

// ---------------- weight split kernels ----------------
__global__ void split_kernel(const float* __restrict__ in, bf16* __restrict__ hi,
                             bf16* __restrict__ lo, int n4)
{
    const int i = blockIdx.x * 256 + threadIdx.x;
    if (i < n4) {
        const float4 v = ((const float4*)in)[i];
        uint32_t h0, l0, h1, l1;
        split2(v.x, v.y, h0, l0);
        split2(v.z, v.w, h1, l1);
        ((uint2*)hi)[i] = make_uint2(h0, h1);
        ((uint2*)lo)[i] = make_uint2(l0, l1);
    }
}

struct SplitJobs {
    const float* src[9];
    size_t off[9];
    int n4[9];
};

__global__ void split_many(SplitJobs j, bf16* __restrict__ hi, bf16* __restrict__ lo)
{
    const int job = blockIdx.y;
    const int i = blockIdx.x * 256 + threadIdx.x;
    if (i < j.n4[job]) {
        const float4 v = ((const float4*)j.src[job])[i];
        uint32_t h0, l0, h1, l1;
        split2(v.x, v.y, h0, l0);
        split2(v.z, v.w, h1, l1);
        ((uint2*)(hi + j.off[job]))[i] = make_uint2(h0, h1);
        ((uint2*)(lo + j.off[job]))[i] = make_uint2(l0, l1);
    }
}

// ---------------- LayerNorm -> split bf16 ----------------
__global__ void ln_kernel(const float* __restrict__ x, const float* __restrict__ gg,
                          const float* __restrict__ bb,
                          bf16* __restrict__ hi, bf16* __restrict__ lo)
{
    __shared__ float red[8];
    const int row = blockIdx.x;
    const int t   = threadIdx.x;
    float4 v = ((const float4*)(x + (size_t)row * DMODEL))[t];
    float s = v.x + v.y + v.z + v.w;
#pragma unroll
    for (int o = 16; o; o >>= 1) s += __shfl_xor_sync(0xffffffffu, s, o);
    if ((t & 31) == 0) red[t >> 5] = s;
    __syncthreads();
    const float mu = (red[0] + red[1] + red[2] + red[3]) * (1.f / DMODEL);
    const float dx = v.x - mu, dy = v.y - mu, dz = v.z - mu, dw = v.w - mu;
    float vs = dx*dx + dy*dy + dz*dz + dw*dw;
#pragma unroll
    for (int o = 16; o; o >>= 1) vs += __shfl_xor_sync(0xffffffffu, vs, o);
    if ((t & 31) == 0) red[4 + (t >> 5)] = vs;
    __syncthreads();
    const float var = (red[4] + red[5] + red[6] + red[7]) * (1.f / DMODEL);
    const float inv = rsqrtf(var + 1e-5f);
    const int i0 = t << 2;
    float ox = dx * inv * gg[i0+0] + bb[i0+0];
    float oy = dy * inv * gg[i0+1] + bb[i0+1];
    float oz = dz * inv * gg[i0+2] + bb[i0+2];
    float ow = dw * inv * gg[i0+3] + bb[i0+3];
    uint32_t h0, l0, h1, l1;
    split2(ox, oy, h0, l0);
    split2(oz, ow, h1, l1);
    ((uint2*)(hi + (size_t)row * DMODEL))[t] = make_uint2(h0, h1);
    ((uint2*)(lo + (size_t)row * DMODEL))[t] = make_uint2(l0, l1);
}

#ifdef HAS_TC5
// ---------------- tcgen05 helpers ----------------
__device__ __forceinline__ uint32_t smem_u32(const void* p) {
    uint32_t a;
    asm("{ .reg .u64 t; cvta.to.shared.u64 t, %1; cvt.u32.u64 %0, t; }" : "=r"(a) : "l"(p));
    return a;
}
__device__ __forceinline__ uint32_t elect1() {
    uint32_t p;
    asm volatile("{\n\t.reg .pred p;\n\telect.sync _|p, 0xFFFFFFFF;\n\tselp.b32 %0, 1, 0, p;\n\t}"
                 : "=r"(p));
    return p;
}
__device__ __forceinline__ uint32_t swz(uint32_t off) { return off ^ ((off >> 3) & 0x70); }

__device__ __forceinline__ void cp16(uint32_t dst, const void* src, int sz) {
    asm volatile("cp.async.cg.shared.global [%0], [%1], 16, %2;"
                 :: "r"(dst), "l"(src), "r"(sz) : "memory");
}

// SW128 K-major smem descriptor (Blackwell): layout=2, version=1, SBO=64, LBO=1
static __device__ __forceinline__ uint64_t mkdesc(uint32_t addr) {
    const uint64_t base = (2ull << 61) | (1ull << 46) | (64ull << 32) | (1ull << 16);
    return base | ((addr >> 4) & 0x3FFFu);
}

__device__ __forceinline__ void mma_f16_ss(uint32_t d, uint64_t a, uint64_t b,
                                           uint32_t idesc, uint32_t en) {
    asm volatile(
        "{\n\t.reg .pred p;\n\tsetp.ne.u32 p, %4, 0;\n\t"
        "tcgen05.mma.cta_group::1.kind::f16 [%0], %1, %2, %3, {%5,%5,%5,%5}, p;\n\t}"
        :: "r"(d), "l"(a), "l"(b), "r"(idesc), "r"(en), "r"(0u) : "memory");
}

__device__ __forceinline__ void mbar_wait(uint32_t mbar, uint32_t parity) {
    asm volatile(
        "{\n\t.reg .pred P;\n\t"
        "W_%=:\n\t"
        "mbarrier.try_wait.parity.acquire.cta.shared::cta.b64 P, [%0], %1, 0x989680;\n\t"
        "@P bra.uni D_%=;\n\t"
        "bra.uni W_%=;\n\t"
        "D_%=:\n\t}"
        :: "r"(mbar), "r"(parity) : "memory");
}

#define TC_LD32(r, addr) \
    asm volatile( \
        "tcgen05.ld.sync.aligned.32x32b.x32.b32 " \
        "{%0, %1, %2, %3, %4, %5, %6, %7, " \
        " %8, %9, %10, %11, %12, %13, %14, %15, " \
        " %16, %17, %18, %19, %20, %21, %22, %23, " \
        " %24, %25, %26, %27, %28, %29, %30, %31}, [%32];" \
        : "=r"((r)[0]),  "=r"((r)[1]),  "=r"((r)[2]),  "=r"((r)[3]), \
          "=r"((r)[4]),  "=r"((r)[5]),  "=r"((r)[6]),  "=r"((r)[7]), \
          "=r"((r)[8]),  "=r"((r)[9]),  "=r"((r)[10]), "=r"((r)[11]), \
          "=r"((r)[12]), "=r"((r)[13]), "=r"((r)[14]), "=r"((r)[15]), \
          "=r"((r)[16]), "=r"((r)[17]), "=r"((r)[18]), "=r"((r)[19]), \
          "=r"((r)[20]), "=r"((r)[21]), "=r"((r)[22]), "=r"((r)[23]), \
          "=r"((r)[24]), "=r"((r)[25]), "=r"((r)[26]), "=r"((r)[27]), \
          "=r"((r)[28]), "=r"((r)[29]), "=r"((r)[30]), "=r"((r)[31]) \
        : "r"(addr))
#else
__device__ __forceinline__ void mma_bf16(float* c, const uint32_t* a, const uint32_t* b) {
    asm volatile("mma.sync.aligned.m16n8k16.row.col.f32.bf16.bf16.f32 "
        "{%0,%1,%2,%3}, {%4,%5,%6,%7}, {%8,%9}, {%0,%1,%2,%3};"
        : "+f"(c[0]), "+f"(c[1]), "+f"(c[2]), "+f"(c[3])
        : "r"(a[0]), "r"(a[1]), "r"(a[2]), "r"(a[3]), "r"(b[0]), "r"(b[1]));
}
#endif

// ---------------- GEMM: C[M,N] = (Ah+Al)[M,K] @ (Wh+Wl)[N,K]^T, 3-pass split -------
// R13 body with 256 threads: fills done by 8 warps (16 cp.async/thread), MMA issue by
// warp 0, epilogue column-split across warp-groups (subpartition = warp&3, implicit).
// 128x128 tiles, BK=64 single-stage, 66.5KB smem -> 3 CTAs/SM (the proven invariant).
// gridDim.z batches directions. M mult of 128, K mult of 64 (fallback: 16).
// EPI: 0 none, 1 softplus(acc+aux[n]), 2 acc+aux[m*N+n], 3 fp32 C + split (Ch,Cl).
#define SM_TOT (1024 + 65536)   // hdr + 4 tiles x 16KB

template<int EPI>
__global__ void __launch_bounds__(256)
gemm5(const bf16* __restrict__ Ah, const bf16* __restrict__ Al, int lda, size_t aStrideZ,
      const bf16* __restrict__ Wh, const bf16* __restrict__ Wl, size_t wStrideZ,
      float* __restrict__ C, size_t cStrideZ, int N, int K,
      const float* __restrict__ aux0, const float* __restrict__ aux1,
      bf16* __restrict__ Ch, bf16* __restrict__ Cl, size_t chStrideZ)
{
    const int z = blockIdx.z;
    Ah += (size_t)z * aStrideZ;  Al += (size_t)z * aStrideZ;
    Wh += (size_t)z * wStrideZ;  Wl += (size_t)z * wStrideZ;
    C  += (size_t)z * cStrideZ;
    const float* aux = z ? aux1 : aux0;
    if (EPI == 3) { Ch += (size_t)z * chStrideZ; Cl += (size_t)z * chStrideZ; }

#ifdef HAS_TC5
    // ================= tcgen05 path (sm_103a SASS), single-stage BK=64 =============
    extern __shared__ __align__(1024) char sm[];
    const uint32_t sb = smem_u32(sm);
    const int tid = threadIdx.x, warp = tid >> 5, lane = tid & 31;
    const int m0 = blockIdx.y << 7, n0 = blockIdx.x << 7;

    if (warp == 0) {
        asm volatile("tcgen05.alloc.cta_group::1.sync.aligned.shared::cta.b32 [%0], %1;"
                     :: "r"(sb), "r"(128u) : "memory");
        asm volatile("tcgen05.relinquish_alloc_permit.cta_group::1.sync.aligned;");
    }
    if (tid == 0)
        asm volatile("mbarrier.init.shared.b64 [%0], %1;" :: "r"(sb + 8), "r"(1u) : "memory");
    __syncthreads();
    uint32_t tmem;
    asm volatile("ld.shared.b32 %0, [%1];" : "=r"(tmem) : "r"(sb));

    const uint32_t idesc = 0x8200490u;   // M=128, N=128, bf16 x bf16 -> f32
    uint32_t phase = 0;

    for (int k0 = 0; k0 < K; k0 += 64) {
        // fill: async 16B copies into SW128-swizzled tiles (8 warps, 16 cp16/thread)
#pragma unroll
        for (int i = 0; i < 4; i++) {
            const int idx = tid + (i << 8);          // 0..1023
            const int r   = idx >> 3;                // row 0..127
            const int ch  = idx & 7;                 // 16B chunk (8 bf16)
            const uint32_t sw = swz((uint32_t)(r * 128 + ch * 16));
            const size_t aoff = (size_t)(m0 + r) * lda + k0 + (ch << 3);
            cp16(sb + 1024 + 0     + sw, Ah + aoff, 16);
            cp16(sb + 1024 + 16384 + sw, Al + aoff, 16);
            const int rb  = (n0 + r < N) ? (n0 + r) : 0;
            const int bsz = (n0 + r < N) ? 16 : 0;
            const size_t boff = (size_t)rb * K + k0 + (ch << 3);
            cp16(sb + 1024 + 32768 + sw, Wh + boff, bsz);
            cp16(sb + 1024 + 49152 + sw, Wl + boff, bsz);
        }
        asm volatile("cp.async.commit_group;" ::: "memory");
        asm volatile("cp.async.wait_group 0;" ::: "memory");
        asm volatile("fence.proxy.async.shared::cta;" ::: "memory");
        __syncthreads();

        if (warp == 0 && elect1()) {
            const uint64_t ah = mkdesc(sb + 1024),         al = mkdesc(sb + 1024 + 16384);
            const uint64_t bh = mkdesc(sb + 1024 + 32768), bl = mkdesc(sb + 1024 + 49152);
#pragma unroll
            for (int kc = 0; kc < 4; kc++) {
                mma_f16_ss(tmem, ah + kc * 2, bh + kc * 2, idesc, (k0 | kc) != 0);
                mma_f16_ss(tmem, ah + kc * 2, bl + kc * 2, idesc, 1u);
                mma_f16_ss(tmem, al + kc * 2, bh + kc * 2, idesc, 1u);
            }
            asm volatile(
                "tcgen05.commit.cta_group::1.mbarrier::arrive::one.shared::cluster.b64 [%0];"
                :: "r"(sb + 8) : "memory");
        }
        mbar_wait(sb + 8, phase);
        phase ^= 1;
    }

    asm volatile("tcgen05.fence::after_thread_sync;" ::: "memory");

    // epilogue: warp w reads subpartition (w&3); column half selected by w>>2
    const int m = m0 + (warp & 3) * 32 + lane;
    const int cb0 = (warp >> 2) << 6;    // 0 or 64
#pragma unroll
    for (int bq = 0; bq < 2; bq++) {
        const int base = cb0 + bq * 32;
        uint32_t r[32];
        TC_LD32(r, tmem + base);
        asm volatile("tcgen05.wait::ld.sync.aligned;" ::: "memory");
#pragma unroll
        for (int j = 0; j < 32; j += 4) {
            const int col = n0 + base + j;
            if (col < N) {
                float4 v = make_float4(__uint_as_float(r[j]),   __uint_as_float(r[j+1]),
                                       __uint_as_float(r[j+2]), __uint_as_float(r[j+3]));
                if (EPI == 1) {
                    const float4 b = *(const float4*)(aux + col);
                    v.x = softplusf(v.x + b.x); v.y = softplusf(v.y + b.y);
                    v.z = softplusf(v.z + b.z); v.w = softplusf(v.w + b.w);
                }
                if (EPI == 2) {
                    const float4 a4 = *(const float4*)(aux + (size_t)m * N + col);
                    v.x += a4.x; v.y += a4.y; v.z += a4.z; v.w += a4.w;
                }
                *(float4*)(C + (size_t)m * N + col) = v;
                if (EPI == 3) {
                    uint32_t h0, l0, h1, l1;
                    split2(v.x, v.y, h0, l0);
                    split2(v.z, v.w, h1, l1);
                    *(uint2*)(Ch + (size_t)m * N + col) = make_uint2(h0, h1);
                    *(uint2*)(Cl + (size_t)m * N + col) = make_uint2(l0, l1);
                }
            }
        }
    }

    __syncthreads();
    if (tid == 0)
        asm volatile("mbarrier.inval.shared.b64 [%0];" :: "r"(sb + 8) : "memory");
    __syncthreads();
    if (warp == 0)
        asm volatile("tcgen05.dealloc.cta_group::1.sync.aligned.b32 %0, %1;"
                     :: "r"(tmem), "r"(128u));
#else
    // ================= mma.sync fallback (compile-only for non-'a' pass) ============
    __shared__ uint32_t sAh[8][136], sAl[8][136], sBh[8][136], sBl[8][136];
    const int tid  = threadIdx.x;
    const int m0   = blockIdx.y << 7;
    const int n0   = blockIdx.x << 7;
    const int lane = tid & 31, warp = tid >> 5;
    const int wm = ((warp & 3) >> 1) << 6, wn = (warp & 1) << 6;
    const int g  = lane >> 2,  t  = lane & 3;

    float acc[4][8][4];
#pragma unroll
    for (int i = 0; i < 4; i++)
#pragma unroll
        for (int j = 0; j < 8; j++)
#pragma unroll
            for (int q = 0; q < 4; q++) acc[i][j][q] = 0.f;

#pragma unroll 1
    for (int k0 = 0; k0 < K; k0 += 16) {
#pragma unroll
        for (int i = 0; i < 4; i++) {
            const int idx = tid + (i << 8);
            const int r   = idx >> 3;
            const int k2  = idx & 7;
            sAh[k2][r] = *(const uint32_t*)(Ah + (size_t)(m0 + r) * lda + k0 + k2 * 2);
            sAl[k2][r] = *(const uint32_t*)(Al + (size_t)(m0 + r) * lda + k0 + k2 * 2);
            uint32_t bh = 0, bl = 0;
            if (n0 + r < N) {
                bh = *(const uint32_t*)(Wh + (size_t)(n0 + r) * K + k0 + k2 * 2);
                bl = *(const uint32_t*)(Wl + (size_t)(n0 + r) * K + k0 + k2 * 2);
            }
            sBh[k2][r] = bh; sBl[k2][r] = bl;
        }
        __syncthreads();

        if (warp < 4) {
            uint32_t bh[8][2], bl[8][2];
#pragma unroll
            for (int nt = 0; nt < 8; nt++) {
                const int nb = wn + (nt << 3) + g;
                bh[nt][0] = sBh[t][nb];     bh[nt][1] = sBh[t+4][nb];
                bl[nt][0] = sBl[t][nb];     bl[nt][1] = sBl[t+4][nb];
            }
#pragma unroll
            for (int mt = 0; mt < 4; mt++) {
                const int mb = wm + (mt << 4) + g;
                uint32_t ah[4] = { sAh[t][mb], sAh[t][mb+8], sAh[t+4][mb], sAh[t+4][mb+8] };
                uint32_t al[4] = { sAl[t][mb], sAl[t][mb+8], sAl[t+4][mb], sAl[t+4][mb+8] };
#pragma unroll
                for (int nt = 0; nt < 8; nt++) {
                    mma_bf16(acc[mt][nt], ah, bh[nt]);
                    mma_bf16(acc[mt][nt], ah, bl[nt]);
                    mma_bf16(acc[mt][nt], al, bh[nt]);
                }
            }
        }
        __syncthreads();
    }

    if (warp < 4) {
#pragma unroll
        for (int mt = 0; mt < 4; mt++) {
            const int r0 = m0 + wm + (mt << 4) + g;
#pragma unroll
            for (int nt = 0; nt < 8; nt++) {
                const int col = n0 + wn + (nt << 3) + (t << 1);
                if (col < N) {
                    float v0 = acc[mt][nt][0], v1 = acc[mt][nt][1];
                    float v2 = acc[mt][nt][2], v3 = acc[mt][nt][3];
                    if (EPI == 1) {
                        const float b0 = __ldg(&aux[col]), b1 = __ldg(&aux[col+1]);
                        v0 = softplusf(v0 + b0); v1 = softplusf(v1 + b1);
                        v2 = softplusf(v2 + b0); v3 = softplusf(v3 + b1);
                    }
                    if (EPI == 2) {
                        const float2 a0 = *(const float2*)(aux + (size_t)r0 * N + col);
                        const float2 a1 = *(const float2*)(aux + (size_t)(r0+8) * N + col);
                        v0 += a0.x; v1 += a0.y; v2 += a1.x; v3 += a1.y;
                    }
                    *(float2*)(C + (size_t)r0     * N + col) = make_float2(v0, v1);
                    *(float2*)(C + (size_t)(r0+8) * N + col) = make_float2(v2, v3);
                    if (EPI == 3) {
                        uint32_t h, l;
                        split2(v0, v1, h, l);
                        *(uint32_t*)(Ch + (size_t)r0 * N + col) = h;
                        *(uint32_t*)(Cl + (size_t)r0 * N + col) = l;
                        split2(v2, v3, h, l);
                        *(uint32_t*)(Ch + (size_t)(r0+8) * N + col) = h;
                        *(uint32_t*)(Cl + (size_t)(r0+8) * N + col) = l;
                    }
                }
            }
        }
    }
#endif
}

// ---------------- depthwise conv (K=4) + SiLU + split, float4, z = direction -------
__global__ void conv_silu_kernel(const float* __restrict__ in, int ldin, size_t inStrideZ,
                                 const float* __restrict__ w0, const float* __restrict__ w1,
                                 const float* __restrict__ b0, const float* __restrict__ b1,
                                 float* __restrict__ outf, size_t outfStrideZ,
                                 bf16* __restrict__ outh, bf16* __restrict__ outl,
                                 size_t outStrideZ)
{
    const int z = blockIdx.z;
    const float* inp  = in + (size_t)z * inStrideZ;
    const float* w    = z ? w1 : w0;
    const float* bias = z ? b1 : b0;
    bf16* oh = outh + (size_t)z * outStrideZ;
    bf16* ol = outl + (size_t)z * outStrideZ;

    const int idx4 = blockIdx.x * 256 + threadIdx.x;
    const int dq   = idx4 & (DI / 4 - 1);
    const int tok  = idx4 >> 8;
    const int l    = tok & (LL - 1);
    const int dd   = dq << 2;
    const float* base = inp + (size_t)(tok - l) * ldin + dd;

    float wr[4][4];
    *(float4*)wr[0] = *(const float4*)(w + (dd+0)*4);
    *(float4*)wr[1] = *(const float4*)(w + (dd+1)*4);
    *(float4*)wr[2] = *(const float4*)(w + (dd+2)*4);
    *(float4*)wr[3] = *(const float4*)(w + (dd+3)*4);
    float4 acc = *(const float4*)(bias + dd);

    if (!z) {
#pragma unroll
        for (int k = 0; k < 4; k++) {
            const int ls = l - 3 + k;
            if (ls >= 0) {
                const float4 v = *(const float4*)(base + (size_t)ls * ldin);
                acc.x = fmaf(v.x, wr[0][k], acc.x);
                acc.y = fmaf(v.y, wr[1][k], acc.y);
                acc.z = fmaf(v.z, wr[2][k], acc.z);
                acc.w = fmaf(v.w, wr[3][k], acc.w);
            }
        }
    } else {
#pragma unroll
        for (int j = 0; j < 4; j++) {
            const int ls = l + j;
            if (ls < LL) {
                const float4 v = *(const float4*)(base + (size_t)ls * ldin);
                acc.x = fmaf(v.x, wr[0][3-j], acc.x);
                acc.y = fmaf(v.y, wr[1][3-j], acc.y);
                acc.z = fmaf(v.z, wr[2][3-j], acc.z);
                acc.w = fmaf(v.w, wr[3][3-j], acc.w);
            }
        }
    }
    float4 s = make_float4(siluf(acc.x), siluf(acc.y), siluf(acc.z), siluf(acc.w));
    if (outf) ((float4*)(outf + (size_t)z * outfStrideZ))[idx4] = s;
    uint32_t h0, l0, h1, l1;
    split2(s.x, s.y, h0, l0);
    split2(s.z, s.w, h1, l1);
    ((uint2*)oh)[idx4] = make_uint2(h0, h1);
    ((uint2*)ol)[idx4] = make_uint2(l0, l1);
}

// ---------------- selective scan + fused gating, z = direction ----------------
__global__ __launch_bounds__(256) void scan_kernel(
    const float* __restrict__ u, size_t uStrideZ,
    const float* __restrict__ dt, size_t dtStrideZ,
    const float* __restrict__ xdbl, size_t xdStrideZ,
    const float* __restrict__ xz, size_t xzStrideZ,
    const float* __restrict__ Alog0, const float* __restrict__ Alog1,
    const float* __restrict__ Dp0, const float* __restrict__ Dp1,
    bf16* __restrict__ ygh, bf16* __restrict__ ygl, size_t ygStrideZ)
{
    __shared__ float s_u[64][16], s_dt[64][16], s_B[64][16], s_C[64][16], s_y[64][16];
    const int z = blockIdx.z;
    const int backward = z;
    const float* up  = u + (size_t)z * uStrideZ;
    const float* dtp = dt + (size_t)z * dtStrideZ;
    const float* xdp = xdbl + (size_t)z * xdStrideZ;
    const float* xzp = xz + (size_t)z * xzStrideZ;
    const float* Alog = z ? Alog1 : Alog0;
    const float* Dp   = z ? Dp1   : Dp0;
    bf16* yh = ygh + (size_t)z * ygStrideZ;
    bf16* yl = ygl + (size_t)z * ygStrideZ;

    const int b     = blockIdx.x >> 6;
    const int dbase = (blockIdx.x & 63) << 4;
    const int tid = threadIdx.x;
    const int dl  = tid >> 4;
    const int n   = tid & 15;
    const int d   = dbase + dl;
    const float a    = -expf(Alog[d * DST + n]);
    const float Dloc = Dp[d];
    float h = 0.f;
    const size_t brow = (size_t)b * LL;

    for (int chunk = 0; chunk < LL / 64; chunk++) {
        const int c0 = chunk << 6;
#pragma unroll
        for (int i = 0; i < 4; i++) {
            const int ii = tid + (i << 8);
            const int tt = ii >> 4, dc = ii & 15;
            const int t = c0 + tt;
            const int l = backward ? (LL - 1 - t) : t;
            const size_t roff = brow + l;
            s_u [tt][dc] = up [roff * DI + dbase + dc];
            s_dt[tt][dc] = dtp[roff * DI + dbase + dc];
            s_B [tt][dc] = xdp[roff * XD + 64 + dc];
            s_C [tt][dc] = xdp[roff * XD + 80 + dc];
        }
        __syncthreads();
#pragma unroll 8
        for (int tt = 0; tt < 64; tt++) {
            const float dtv = s_dt[tt][dl];
            const float uv  = s_u [tt][dl];
            const float dA  = __expf(dtv * a);
            const float db  = dtv * uv * s_B[tt][n];
            h = fmaf(dA, h, db);
            float yp = h * s_C[tt][n];
            yp += __shfl_xor_sync(0xffffffffu, yp, 8);
            yp += __shfl_xor_sync(0xffffffffu, yp, 4);
            yp += __shfl_xor_sync(0xffffffffu, yp, 2);
            yp += __shfl_xor_sync(0xffffffffu, yp, 1);
            if (n == 0) s_y[tt][dl] = fmaf(uv, Dloc, yp);
        }
        __syncthreads();
#pragma unroll
        for (int i = 0; i < 4; i++) {
            const int ii = tid + (i << 8);
            const int tt = ii >> 4, dc = ii & 15;
            const int t = c0 + tt;
            const int l = backward ? (LL - 1 - t) : t;
            const size_t roff = brow + l;
            const float zz = xzp[roff * DI2 + DI + dbase + dc];
            const float v = s_y[tt][dc] * siluf(zz);
            const bf16 hv = __float2bfloat16(v);
            yh[roff * DI + dbase + dc] = hv;
            yl[roff * DI + dbase + dc] = __float2bfloat16(v - __bfloat162float(hv));
        }
        __syncthreads();
    }
}

// ---------------- final gate/concat -> split bf16 ----------------
__global__ void ymix_kernel(const float* __restrict__ mo0, const float* __restrict__ mo1,
                            const float* __restrict__ xp,
                            bf16* __restrict__ ymh, bf16* __restrict__ yml)
{
    const int idx = blockIdx.x * 256 + threadIdx.x;
    const int dd  = idx & (DI - 1);
    const int tok = idx >> 10;
    const float g = siluf(xp[(size_t)tok * DI2 + DI + dd]);
    const float v0 = mo0[idx] * g;
    const float v1 = mo1[idx] * g;
    const bf16 h0 = __float2bfloat16(v0);
    const bf16 h1 = __float2bfloat16(v1);
    ymh[(size_t)tok * DI2 + dd]      = h0;
    yml[(size_t)tok * DI2 + dd]      = __float2bfloat16(v0 - __bfloat162float(h0));
    ymh[(size_t)tok * DI2 + DI + dd] = h1;
    yml[(size_t)tok * DI2 + DI + dd] = __float2bfloat16(v1 - __bfloat162float(h1));
}

// ---------------- host ----------------
extern "C" void kernel_launch(void* const* d_in, const int* in_sizes, int n_in,
                              void* d_out, int out_size)
{
    const float* x      = (const float*)d_in[0];
    const float* norm_g = (const float*)d_in[1];
    const float* norm_b = (const float*)d_in[2];
    const float* in_w   = (const float*)d_in[3];
    const float* conv_w = (const float*)d_in[4];
    const float* conv_b = (const float*)d_in[5];
    const float* out_w  = (const float*)d_in[6];
    const float* P[2][9];
    for (int p = 0; p < 2; p++)
        for (int i = 0; i < 9; i++)
            P[p][i] = (const float*)d_in[7 + p * 9 + i];
    // P[p]: 0 in_w, 1 conv_w, 2 conv_b, 3 xp_w, 4 dt_w, 5 dt_b, 6 Alog, 7 D, 8 out_w

    cudaFuncSetAttribute(gemm5<0>, cudaFuncAttributeMaxDynamicSharedMemorySize, SM_TOT);
    cudaFuncSetAttribute(gemm5<1>, cudaFuncAttributeMaxDynamicSharedMemorySize, SM_TOT);
    cudaFuncSetAttribute(gemm5<2>, cudaFuncAttributeMaxDynamicSharedMemorySize, SM_TOT);
    cudaFuncSetAttribute(gemm5<3>, cudaFuncAttributeMaxDynamicSharedMemorySize, SM_TOT);

    float *xp, *xz, *xma, *xdbl, *dtb;
    bf16 *xnh, *xnl, *xah, *xal, *xmh, *xml, *xdh, *xdl, *ygh, *ygl, *ymh, *yml, *wH, *wL;
    cudaGetSymbolAddress((void**)&xp,   g_xp);
    cudaGetSymbolAddress((void**)&xz,   g_xz);
    cudaGetSymbolAddress((void**)&xma,  g_xma);
    cudaGetSymbolAddress((void**)&xdbl, g_xdbl);
    cudaGetSymbolAddress((void**)&dtb,  g_dt);
    cudaGetSymbolAddress((void**)&xnh,  g_xnh);  cudaGetSymbolAddress((void**)&xnl, g_xnl);
    cudaGetSymbolAddress((void**)&xah,  g_xah);  cudaGetSymbolAddress((void**)&xal, g_xal);
    cudaGetSymbolAddress((void**)&xmh,  g_xmh);  cudaGetSymbolAddress((void**)&xml, g_xml);
    cudaGetSymbolAddress((void**)&xdh,  g_xdh);  cudaGetSymbolAddress((void**)&xdl, g_xdl);
    cudaGetSymbolAddress((void**)&ygh,  g_ygh);  cudaGetSymbolAddress((void**)&ygl, g_ygl);
    cudaGetSymbolAddress((void**)&ymh,  g_ymh);  cudaGetSymbolAddress((void**)&yml, g_yml);
    cudaGetSymbolAddress((void**)&wH,   g_wH);   cudaGetSymbolAddress((void**)&wL,  g_wL);

    float* mo = dtb;                 // alias: dt dead after scan, before mo GEMM
    const size_t SDI  = (size_t)NTOK * DI;
    const size_t SDI2 = (size_t)NTOK * DI2;
    const size_t SXD  = (size_t)NTOK * XD;
    const int MB = NTOK / 128;
    const int CONV_GRID = NTOK * DI / 4 / 256;

    const size_t SZ_IN   = (size_t)DI2 * DMODEL;
    const size_t SZ_PIN  = (size_t)DI2 * DI;
    const size_t SZ_XP   = (size_t)XD * DI;
    const size_t SZ_DT   = (size_t)DI * DTR;
    const size_t SZ_POUT = (size_t)DI * DI;
    const size_t SZ_OUT  = (size_t)DMODEL * DI2;
    const size_t OFF_IN    = 0;
    const size_t OFF_P0IN  = OFF_IN + SZ_IN;
    const size_t OFF_P1IN  = OFF_P0IN + SZ_PIN;
    const size_t OFF_P0XP  = OFF_P1IN + SZ_PIN;
    const size_t OFF_P1XP  = OFF_P0XP + SZ_XP;
    const size_t OFF_P0DT  = OFF_P1XP + SZ_XP;
    const size_t OFF_P1DT  = OFF_P0DT + SZ_DT;
    const size_t OFF_P0OUT = OFF_P1DT + SZ_DT;
    const size_t OFF_P1OUT = OFF_P0OUT + SZ_POUT;
    const size_t OFF_OUT   = OFF_P1OUT + SZ_POUT;

    // 0: LN -> split xn
    ln_kernel<<<NTOK, 128>>>(x, norm_g, norm_b, xnh, xnl);

    // 1: split in_w
    split_kernel<<<(int)(SZ_IN / 4 / 256), 256>>>(in_w, wH + OFF_IN, wL + OFF_IN,
                                                  (int)(SZ_IN / 4));
    // 2: xp = xn @ in_w^T
    gemm5<0><<<dim3(DI2/128, MB, 1), 256, SM_TOT>>>(
        xnh, xnl, DMODEL, 0, wH + OFF_IN, wL + OFF_IN, 0, xp, 0, DI2, DMODEL,
        nullptr, nullptr, nullptr, nullptr, 0);

    // 3: xa = silu(causal dwconv(xp[:, :DI])) -> split only
    conv_silu_kernel<<<dim3(CONV_GRID, 1, 1), 256>>>(
        xp, DI2, 0, conv_w, conv_w, conv_b, conv_b, nullptr, 0, xah, xal, 0);

    // 4: split all remaining weights (9 jobs, one launch)
    {
        SplitJobs j;
        j.src[0] = P[0][0]; j.off[0] = OFF_P0IN;  j.n4[0] = (int)(SZ_PIN / 4);
        j.src[1] = P[1][0]; j.off[1] = OFF_P1IN;  j.n4[1] = (int)(SZ_PIN / 4);
        j.src[2] = P[0][3]; j.off[2] = OFF_P0XP;  j.n4[2] = (int)(SZ_XP / 4);
        j.src[3] = P[1][3]; j.off[3] = OFF_P1XP;  j.n4[3] = (int)(SZ_XP / 4);
        j.src[4] = P[0][4]; j.off[4] = OFF_P0DT;  j.n4[4] = (int)(SZ_DT / 4);
        j.src[5] = P[1][4]; j.off[5] = OFF_P1DT;  j.n4[5] = (int)(SZ_DT / 4);
        j.src[6] = P[0][8]; j.off[6] = OFF_P0OUT; j.n4[6] = (int)(SZ_POUT / 4);
        j.src[7] = P[1][8]; j.off[7] = OFF_P1OUT; j.n4[7] = (int)(SZ_POUT / 4);
        j.src[8] = out_w;   j.off[8] = OFF_OUT;   j.n4[8] = (int)(SZ_OUT / 4);
        split_many<<<dim3((int)(SZ_PIN / 4 / 256), 9), 256>>>(j, wH, wL);
    }

    // 5: xz[p] = xa @ P[p].in_w^T, z = direction
    gemm5<0><<<dim3(DI2/128, MB, 2), 256, SM_TOT>>>(
        xah, xal, DI, 0, wH + OFF_P0IN, wL + OFF_P0IN, SZ_PIN, xz, SDI2, DI2, DI,
        nullptr, nullptr, nullptr, nullptr, 0);

    // 6: xm[p] = silu(dwconv_p(xz[p][:, :DI])) -> fp32 (scan u) + split
    conv_silu_kernel<<<dim3(CONV_GRID, 1, 2), 256>>>(
        xz, DI2, SDI2, P[0][1], P[1][1], P[0][2], P[1][2], xma, SDI, xmh, xml, SDI);

    // 7: xdbl[p] = xm[p] @ xp_w^T -> fp32 + split
    gemm5<3><<<dim3(1, MB, 2), 256, SM_TOT>>>(
        xmh, xml, DI, SDI, wH + OFF_P0XP, wL + OFF_P0XP, SZ_XP, xdbl, SXD, XD, DI,
        nullptr, nullptr, xdh, xdl, SXD);

    // 8: dt[p] = softplus(xdbl[p][:, :64] @ dt_w^T + dt_b)
    gemm5<1><<<dim3(DI/128, MB, 2), 256, SM_TOT>>>(
        xdh, xdl, XD, SXD, wH + OFF_P0DT, wL + OFF_P0DT, SZ_DT, dtb, SDI, DI, DTR,
        P[0][5], P[1][5], nullptr, nullptr, 0);

    // 9: scan[p] + fused y*silu(z) -> split yg[p]
    scan_kernel<<<dim3(BN_ * (DI/16), 1, 2), 256>>>(
        xma, SDI, dtb, SDI, xdbl, SXD, xz, SDI2,
        P[0][6], P[1][6], P[0][7], P[1][7], ygh, ygl, SDI);

    // 10: mo[p] = yg[p] @ out_w^T (mo aliases dtb; dt dead after scan)
    gemm5<0><<<dim3(DI/128, MB, 2), 256, SM_TOT>>>(
        ygh, ygl, DI, SDI, wH + OFF_P0OUT, wL + OFF_P0OUT, SZ_POUT, mo, SDI, DI, DI,
        nullptr, nullptr, nullptr, nullptr, 0);

    // 11: ym = [yf*g, yb*g] -> split
    ymix_kernel<<<NTOK * DI / 256, 256>>>(mo, mo + SDI, xp, ymh, yml);

    // 12: out = ym @ out_w^T + x
    gemm5<2><<<dim3(DMODEL/128, MB, 1), 256, SM_TOT>>>(
        ymh, yml, DI2, 0, wH + OFF_OUT, wL + OFF_OUT, 0, (float*)d_out, 0, DMODEL, DI2,
        x, nullptr, nullptr, nullptr, 0);
}